// round 6
// baseline (speedup 1.0000x reference)
#include <cuda_runtime.h>
#include <cuda_bf16.h>
#include <cstdint>
#include <cstddef>

#define NR 16384
#define DX 1024
#define DH 2048

// ---------------- device scratch (no dynamic allocation allowed) -----------
__device__ __align__(16) __nv_bfloat16 g_X1b[(size_t)NR * DX];
__device__ __align__(16) __nv_bfloat16 g_X2b[(size_t)NR * DX];
__device__ __align__(16) __nv_bfloat16 g_W1h[(size_t)DX * DH];
__device__ __align__(16) __nv_bfloat16 g_W2h[(size_t)DX * DH];
__device__ __align__(16) __nv_bfloat16 g_H1b[(size_t)NR * DH];
__device__ __align__(16) __nv_bfloat16 g_H2b[(size_t)NR * DH];
__device__ __align__(16) uint8_t g_H1q[(size_t)NR * DH];   // e4m3, x16
__device__ __align__(16) uint8_t g_H2q[(size_t)NR * DH];
__device__ __align__(16) uint8_t g_Wq0[(size_t)DX * DH];   // wh2_W^T e4m3 x512
__device__ __align__(16) uint8_t g_Wq1[(size_t)DX * DH];   // wh1_W^T e4m3 x512
__device__ float g_row1[NR];
__device__ float g_row2[NR];
__device__ float g_L34[NR];

// ---------------- helpers --------------------------------------------------
__device__ __forceinline__ uint32_t smem_u32(const void* p) {
    uint32_t a;
    asm("{ .reg .u64 t; cvta.to.shared.u64 t, %1; cvt.u32.u64 %0, t; }"
        : "=r"(a) : "l"(p));
    return a;
}
__device__ __forceinline__ void cp16(uint32_t dst, const void* src) {
    uint64_t g;
    asm("cvta.to.global.u64 %0, %1;" : "=l"(g) : "l"(src));
    asm volatile("cp.async.cg.shared.global [%0], [%1], 16;"
                 :: "r"(dst), "l"(g) : "memory");
}
#define CP_COMMIT asm volatile("cp.async.commit_group;" ::: "memory")
#define CP_WAIT(n) asm volatile("cp.async.wait_group %0;" :: "n"(n) : "memory")

// pack (hi,lo) floats -> 2 e4m3 bytes; first asm source -> upper byte
__device__ __forceinline__ uint16_t pack_e4m3(float hi, float lo) {
    uint16_t u;
    asm("cvt.rn.satfinite.e4m3x2.f32 %0, %1, %2;" : "=h"(u) : "f"(hi), "f"(lo));
    return u;
}

// ---------------- converts / init ------------------------------------------
__global__ void f2bf_kernel(const float* __restrict__ src, int sel, int n) {
    __nv_bfloat16* dst = (sel == 0) ? g_X1b : (sel == 1) ? g_X2b
                        : (sel == 2) ? g_W1h : g_W2h;
    int i = blockIdx.x * blockDim.x + threadIdx.x;
    int stride = gridDim.x * blockDim.x;
    for (int idx = i * 4; idx < n; idx += stride * 4) {
        float4 v = *(const float4*)&src[idx];
        __nv_bfloat162 lo = __floats2bfloat162_rn(v.x, v.y);
        __nv_bfloat162 hi = __floats2bfloat162_rn(v.z, v.w);
        *(uint32_t*)&dst[idx]     = *(uint32_t*)&lo;
        *(uint32_t*)&dst[idx + 2] = *(uint32_t*)&hi;
    }
}

// transpose+quantize: src fp32 [DH][DX] -> dst e4m3 [DX][DH], scale 512
__global__ void tposeq_kernel(const float* __restrict__ src, int sel) {
    __shared__ float t[32][33];
    uint8_t* dst = sel ? g_Wq1 : g_Wq0;
    int tx = threadIdx.x, ty = threadIdx.y;
    int x = blockIdx.x * 32 + tx;                 // 0..DX
    #pragma unroll
    for (int i = 0; i < 4; i++) {
        int y = blockIdx.y * 32 + ty + i * 8;     // 0..DH
        t[ty + i * 8][tx] = src[(size_t)y * DX + x];
    }
    __syncthreads();
    int x2 = blockIdx.y * 32 + tx;                // k in 0..DH
    #pragma unroll
    for (int i = 0; i < 4; i++) {
        int y2 = blockIdx.x * 32 + ty + i * 8;    // n in 0..DX
        uint16_t u = pack_e4m3(0.f, t[tx][ty + i * 8] * 512.f);
        dst[(size_t)y2 * DH + x2] = (uint8_t)u;
    }
}

__global__ void zero_rows_kernel() {
    int i = blockIdx.x * blockDim.x + threadIdx.x;
    if (i < NR) { g_row1[i] = 0.f; g_row2[i] = 0.f; }
}

// ---------------- bf16 H-GEMM: H = X * W + b  (z: 0->H1, 1->H2) -------------
__launch_bounds__(256, 2)
__global__ void gemmH(const float* __restrict__ b0p,
                      const float* __restrict__ b1p) {
    const int z = blockIdx.z;
    const __nv_bfloat16* A = z ? g_X2b : g_X1b;
    const __nv_bfloat16* B = z ? g_W2h : g_W1h;
    __nv_bfloat16* Hout = z ? g_H2b : g_H1b;
    uint8_t* Hq = z ? g_H2q : g_H1q;
    const float* bias = z ? b1p : b0p;

    __shared__ __align__(16) __nv_bfloat16 smA[2][128][40];
    __shared__ __align__(16) __nv_bfloat16 smB[2][32][136];

    const int tid = threadIdx.x, lane = tid & 31, wid = tid >> 5;
    const int wm = wid >> 2, wn = wid & 3;
    const int brow = blockIdx.y * 128, bcol = blockIdx.x * 128;

    float c[4][4][4];
    #pragma unroll
    for (int i = 0; i < 4; i++)
        #pragma unroll
        for (int j = 0; j < 4; j++)
            #pragma unroll
            for (int k = 0; k < 4; k++) c[i][j][k] = 0.f;

    auto loadA = [&](int st, int k0) {
        #pragma unroll
        for (int i = 0; i < 2; i++) {
            int id = tid + i * 256;
            int r = id >> 2, kc = (id & 3) * 8;
            cp16(smem_u32(&smA[st][r][kc]),
                 &A[(size_t)(brow + r) * DX + k0 + kc]);
        }
    };
    auto loadB = [&](int st, int k0) {
        #pragma unroll
        for (int i = 0; i < 2; i++) {
            int id = tid + i * 256;
            int r = id >> 4, nc = (id & 15) * 8;
            cp16(smem_u32(&smB[st][r][nc]),
                 &B[(size_t)(k0 + r) * DH + bcol + nc]);
        }
    };

    loadA(0, 0); loadB(0, 0); CP_COMMIT;
    const int nk = DX / 32;
    for (int kt = 0; kt < nk; kt++) {
        const int cur = kt & 1, nxt = cur ^ 1;
        if (kt + 1 < nk) { loadA(nxt, (kt + 1) * 32); loadB(nxt, (kt + 1) * 32);
                           CP_COMMIT; CP_WAIT(1); }
        else             { CP_WAIT(0); }
        __syncthreads();

        #pragma unroll
        for (int ks = 0; ks < 32; ks += 16) {
            uint32_t a[4][4];
            #pragma unroll
            for (int mt = 0; mt < 4; mt++) {
                uint32_t ad = smem_u32(
                    &smA[cur][wm * 64 + mt * 16 + (lane & 15)][ks + (lane >> 4) * 8]);
                asm volatile(
                    "ldmatrix.sync.aligned.m8n8.x4.shared.b16 {%0,%1,%2,%3},[%4];"
                    : "=r"(a[mt][0]), "=r"(a[mt][1]), "=r"(a[mt][2]), "=r"(a[mt][3])
                    : "r"(ad));
            }
            uint32_t b[2][4];
            #pragma unroll
            for (int np = 0; np < 2; np++) {
                uint32_t ad = smem_u32(
                    &smB[cur][ks + (lane & 15)][wn * 32 + np * 16 + (lane >> 4) * 8]);
                asm volatile(
                    "ldmatrix.sync.aligned.m8n8.x4.trans.shared.b16 {%0,%1,%2,%3},[%4];"
                    : "=r"(b[np][0]), "=r"(b[np][1]), "=r"(b[np][2]), "=r"(b[np][3])
                    : "r"(ad));
            }
            #pragma unroll
            for (int mt = 0; mt < 4; mt++)
                #pragma unroll
                for (int nt = 0; nt < 4; nt++) {
                    uint32_t b0 = b[nt >> 1][(nt & 1) * 2];
                    uint32_t b1 = b[nt >> 1][(nt & 1) * 2 + 1];
                    asm volatile(
                        "mma.sync.aligned.m16n8k16.row.col.f32.bf16.bf16.f32 "
                        "{%0,%1,%2,%3},{%4,%5,%6,%7},{%8,%9},{%0,%1,%2,%3};"
                        : "+f"(c[mt][nt][0]), "+f"(c[mt][nt][1]),
                          "+f"(c[mt][nt][2]), "+f"(c[mt][nt][3])
                        : "r"(a[mt][0]), "r"(a[mt][1]), "r"(a[mt][2]), "r"(a[mt][3]),
                          "r"(b0), "r"(b1));
                }
        }
        __syncthreads();
    }

    // epilogue: bf16 H + e4m3 (H*16)
    #pragma unroll
    for (int mt = 0; mt < 4; mt++) {
        int r0 = brow + wm * 64 + mt * 16 + (lane >> 2);
        #pragma unroll
        for (int nt = 0; nt < 4; nt++) {
            int col = bcol + wn * 32 + nt * 8 + 2 * (lane & 3);
            float b0 = bias[col], b1 = bias[col + 1];
            float f0 = c[mt][nt][0] + b0, f1 = c[mt][nt][1] + b1;
            float f2 = c[mt][nt][2] + b0, f3 = c[mt][nt][3] + b1;
            __nv_bfloat162 v0 = __floats2bfloat162_rn(f0, f1);
            __nv_bfloat162 v1 = __floats2bfloat162_rn(f2, f3);
            *(__nv_bfloat162*)&Hout[(size_t)r0 * DH + col] = v0;
            *(__nv_bfloat162*)&Hout[(size_t)(r0 + 8) * DH + col] = v1;
            *(uint16_t*)&Hq[(size_t)r0 * DH + col] = pack_e4m3(f1 * 16.f, f0 * 16.f);
            *(uint16_t*)&Hq[(size_t)(r0 + 8) * DH + col] =
                pack_e4m3(f3 * 16.f, f2 * 16.f);
        }
    }
}

// ---------------- fp8 X-GEMM: rowbuf[r] += sum_col (H*W/8192 + b - X)^2 -----
// A = Hq [NR][2048] e4m3 (x16), B = WqT [1024][2048] e4m3 (x512)
__launch_bounds__(256, 2)
__global__ void gemmQ(const float* __restrict__ b0p, const float* __restrict__ b1p,
                      const float* __restrict__ x0p, const float* __restrict__ x1p) {
    const int z = blockIdx.z;
    const uint8_t* A = z ? g_H2q : g_H1q;
    const uint8_t* B = z ? g_Wq1 : g_Wq0;
    const float* bias = z ? b1p : b0p;     // z0: wh2b, z1: wh1b
    const float* Xref = z ? x1p : x0p;     // z0: X2,   z1: X1
    float* rowbuf = z ? g_row2 : g_row1;

    __shared__ __align__(16) uint8_t sA[2][128][80];
    __shared__ __align__(16) uint8_t sB[2][128][80];

    const int tid = threadIdx.x, lane = tid & 31, wid = tid >> 5;
    const int wm = wid >> 2, wn = wid & 3;
    const int brow = blockIdx.y * 128, bcol = blockIdx.x * 128;
    const int g = lane >> 2, t4 = (lane & 3) * 4;

    float c[4][4][4];
    #pragma unroll
    for (int i = 0; i < 4; i++)
        #pragma unroll
        for (int j = 0; j < 4; j++)
            #pragma unroll
            for (int k = 0; k < 4; k++) c[i][j][k] = 0.f;

    auto ld = [&](int st, int k0) {
        #pragma unroll
        for (int i = 0; i < 2; i++) {
            int id = tid + i * 256;
            int r = id >> 2, cs = (id & 3) * 16;
            cp16(smem_u32(&sA[st][r][cs]), &A[(size_t)(brow + r) * DH + k0 + cs]);
            cp16(smem_u32(&sB[st][r][cs]), &B[(size_t)(bcol + r) * DH + k0 + cs]);
        }
    };

    ld(0, 0); CP_COMMIT;
    const int nk = DH / 64;
    for (int kt = 0; kt < nk; kt++) {
        const int cur = kt & 1, nxt = cur ^ 1;
        if (kt + 1 < nk) { ld(nxt, (kt + 1) * 64); CP_COMMIT; CP_WAIT(1); }
        else             { CP_WAIT(0); }
        __syncthreads();

        #pragma unroll
        for (int ks = 0; ks < 64; ks += 32) {
            uint32_t a[4][4], b[4][2];
            #pragma unroll
            for (int mt = 0; mt < 4; mt++) {
                const uint8_t* p = &sA[cur][wm * 64 + mt * 16 + g][ks + t4];
                a[mt][0] = *(const uint32_t*)p;
                a[mt][1] = *(const uint32_t*)(p + 8 * 80);
                a[mt][2] = *(const uint32_t*)(p + 16);
                a[mt][3] = *(const uint32_t*)(p + 8 * 80 + 16);
            }
            #pragma unroll
            for (int nt = 0; nt < 4; nt++) {
                const uint8_t* p = &sB[cur][wn * 32 + nt * 8 + g][ks + t4];
                b[nt][0] = *(const uint32_t*)p;
                b[nt][1] = *(const uint32_t*)(p + 16);
            }
            #pragma unroll
            for (int mt = 0; mt < 4; mt++)
                #pragma unroll
                for (int nt = 0; nt < 4; nt++)
                    asm volatile(
                        "mma.sync.aligned.m16n8k32.row.col.f32.e4m3.e4m3.f32 "
                        "{%0,%1,%2,%3},{%4,%5,%6,%7},{%8,%9},{%0,%1,%2,%3};"
                        : "+f"(c[mt][nt][0]), "+f"(c[mt][nt][1]),
                          "+f"(c[mt][nt][2]), "+f"(c[mt][nt][3])
                        : "r"(a[mt][0]), "r"(a[mt][1]), "r"(a[mt][2]), "r"(a[mt][3]),
                          "r"(b[nt][0]), "r"(b[nt][1]));
        }
        __syncthreads();
    }

    const float INV = 1.f / 8192.f;
    #pragma unroll
    for (int mt = 0; mt < 4; mt++)
        #pragma unroll
        for (int half = 0; half < 2; half++) {
            int r = brow + wm * 64 + mt * 16 + (lane >> 2) + half * 8;
            float s = 0.f;
            #pragma unroll
            for (int nt = 0; nt < 4; nt++) {
                int col = bcol + wn * 32 + nt * 8 + 2 * (lane & 3);
                const float* xr = &Xref[(size_t)r * DX + col];
                float d0 = c[mt][nt][half * 2 + 0] * INV + bias[col]     - xr[0];
                float d1 = c[mt][nt][half * 2 + 1] * INV + bias[col + 1] - xr[1];
                s += d0 * d0 + d1 * d1;
            }
            s += __shfl_xor_sync(0xffffffffu, s, 1);
            s += __shfl_xor_sync(0xffffffffu, s, 2);
            if ((lane & 3) == 0) atomicAdd(&rowbuf[r], s);
        }
}

// ---------------- L3^2 + L4^2 per row --------------------------------------
__global__ void l34_kernel(const float* __restrict__ whoW,
                           const float* __restrict__ whob,
                           const float* __restrict__ Y) {
    int wid = threadIdx.x >> 5, lane = threadIdx.x & 31;
    int r = blockIdx.x * 8 + wid;
    const __nv_bfloat16* h1 = &g_H1b[(size_t)r * DH];
    const __nv_bfloat16* h2 = &g_H2b[(size_t)r * DH];
    float s3 = 0.f, dot = 0.f;
    for (int k = lane * 4; k < DH; k += 128) {
        uint2 u1 = *(const uint2*)&h1[k];
        uint2 u2 = *(const uint2*)&h2[k];
        float4 w = *(const float4*)&whoW[k];
        float2 f1a = __bfloat1622float2(*(__nv_bfloat162*)&u1.x);
        float2 f1b = __bfloat1622float2(*(__nv_bfloat162*)&u1.y);
        float2 f2a = __bfloat1622float2(*(__nv_bfloat162*)&u2.x);
        float2 f2b = __bfloat1622float2(*(__nv_bfloat162*)&u2.y);
        float d;
        d = f1a.x - f2a.x; s3 += d * d; dot += (f1a.x + f2a.x) * w.x;
        d = f1a.y - f2a.y; s3 += d * d; dot += (f1a.y + f2a.y) * w.y;
        d = f1b.x - f2b.x; s3 += d * d; dot += (f1b.x + f2b.x) * w.z;
        d = f1b.y - f2b.y; s3 += d * d; dot += (f1b.y + f2b.y) * w.w;
    }
    #pragma unroll
    for (int o = 16; o; o >>= 1) {
        s3  += __shfl_xor_sync(0xffffffffu, s3, o);
        dot += __shfl_xor_sync(0xffffffffu, dot, o);
    }
    if (lane == 0) {
        float L4 = 0.5f * (dot + whob[0]) - Y[r];
        g_L34[r] = s3 * s3 + L4 * L4;
    }
}

// ---------------- final scalar reduction (double) ---------------------------
__global__ void final_reduce_kernel(float* out) {
    __shared__ double sm[32];
    double s = 0.0;
    for (int r = threadIdx.x; r < NR; r += 1024) {
        double a = (double)g_row1[r], b = (double)g_row2[r];
        s += a * a + b * b + (double)g_L34[r];
    }
    #pragma unroll
    for (int o = 16; o; o >>= 1) s += __shfl_xor_sync(0xffffffffu, s, o);
    if ((threadIdx.x & 31) == 0) sm[threadIdx.x >> 5] = s;
    __syncthreads();
    if (threadIdx.x < 32) {
        double v = sm[threadIdx.x];
        #pragma unroll
        for (int o = 16; o; o >>= 1) v += __shfl_xor_sync(0xffffffffu, v, o);
        if (threadIdx.x == 0) out[0] = (float)v;
    }
}

// ---------------- launch -----------------------------------------------------
extern "C" void kernel_launch(void* const* d_in, const int* in_sizes, int n_in,
                              void* d_out, int out_size) {
    const float* X1   = (const float*)d_in[0];
    const float* X2   = (const float*)d_in[1];
    const float* Y    = (const float*)d_in[2];
    const float* w1hW = (const float*)d_in[3];
    const float* w1hb = (const float*)d_in[4];
    const float* w2hW = (const float*)d_in[5];
    const float* w2hb = (const float*)d_in[6];
    const float* wh1W = (const float*)d_in[7];
    const float* wh1b = (const float*)d_in[8];
    const float* wh2W = (const float*)d_in[9];
    const float* wh2b = (const float*)d_in[10];
    const float* whoW = (const float*)d_in[11];
    const float* whob = (const float*)d_in[12];

    f2bf_kernel<<<2048, 256>>>(X1,   0, NR * DX);
    f2bf_kernel<<<2048, 256>>>(X2,   1, NR * DX);
    f2bf_kernel<<<512,  256>>>(w1hW, 2, DX * DH);
    f2bf_kernel<<<512,  256>>>(w2hW, 3, DX * DH);
    tposeq_kernel<<<dim3(32, 64), dim3(32, 8)>>>(wh2W, 0);
    tposeq_kernel<<<dim3(32, 64), dim3(32, 8)>>>(wh1W, 1);
    zero_rows_kernel<<<(NR + 255) / 256, 256>>>();

    gemmH<<<dim3(DH / 128, NR / 128, 2), 256>>>(w1hb, w2hb);
    l34_kernel<<<NR / 8, 256>>>(whoW, whob, Y);
    gemmQ<<<dim3(DX / 128, NR / 128, 2), 256>>>(wh2b, wh1b, X2, X1);

    final_reduce_kernel<<<1, 1024>>>((float*)d_out);
}

// round 7
// speedup vs baseline: 1.2013x; 1.2013x over previous
#include <cuda_runtime.h>
#include <cuda_bf16.h>
#include <cstdint>
#include <cstddef>

#define NR 16384
#define DX 1024
#define DH 2048

// ---------------- device scratch (no dynamic allocation allowed) -----------
__device__ __align__(16) __nv_bfloat16 g_Zb[(size_t)NR * 2048];     // [X1|X2]
__device__ __align__(16) __nv_bfloat16 g_Wst[(size_t)2048 * 2048];  // [W1h;-W2h]
__device__ __align__(16) __nv_bfloat16 g_W2hb[(size_t)1024 * 2048];
__device__ __align__(16) __nv_bfloat16 g_Wh1b[(size_t)2048 * 1024];
__device__ __align__(16) __nv_bfloat16 g_Wh2b[(size_t)2048 * 1024];
__device__ __align__(16) __nv_bfloat16 g_M12[(size_t)1024 * 1024];
__device__ __align__(16) __nv_bfloat16 g_M21[(size_t)1024 * 1024];
__device__ float g_b12[1024];
__device__ float g_b21[1024];
__device__ float g_db[2048];
__device__ float g_v[2048];
__device__ float g_c0[1];
__device__ float g_row1[NR];
__device__ float g_row2[NR];
__device__ float g_row3[NR];
__device__ float g_L4sq[NR];

// ---------------- helpers --------------------------------------------------
__device__ __forceinline__ uint32_t smem_u32(const void* p) {
    uint32_t a;
    asm("{ .reg .u64 t; cvta.to.shared.u64 t, %1; cvt.u32.u64 %0, t; }"
        : "=r"(a) : "l"(p));
    return a;
}
__device__ __forceinline__ void cp16(uint32_t dst, const void* src) {
    uint64_t g;
    asm("cvta.to.global.u64 %0, %1;" : "=l"(g) : "l"(src));
    asm volatile("cp.async.cg.shared.global [%0], [%1], 16;"
                 :: "r"(dst), "l"(g) : "memory");
}
#define CP_COMMIT asm volatile("cp.async.commit_group;" ::: "memory")
#define CP_WAIT(n) asm volatile("cp.async.wait_group %0;" :: "n"(n) : "memory")

// ---------------- converts / init ------------------------------------------
// Z[r][0:1024] = bf16(X1[r]), Z[r][1024:2048] = bf16(X2[r])
__global__ void convz_kernel(const float* __restrict__ X1,
                             const float* __restrict__ X2) {
    int i = blockIdx.x * blockDim.x + threadIdx.x;
    int stride = gridDim.x * blockDim.x;
    for (; i < NR * 256; i += stride) {
        int r = i >> 8, c = (i & 255) * 4;
        float4 a = *(const float4*)&X1[(size_t)r * 1024 + c];
        float4 b = *(const float4*)&X2[(size_t)r * 1024 + c];
        __nv_bfloat162 a0 = __floats2bfloat162_rn(a.x, a.y);
        __nv_bfloat162 a1 = __floats2bfloat162_rn(a.z, a.w);
        __nv_bfloat162 b0 = __floats2bfloat162_rn(b.x, b.y);
        __nv_bfloat162 b1 = __floats2bfloat162_rn(b.z, b.w);
        size_t o = (size_t)r * 2048 + c;
        *(uint32_t*)&g_Zb[o]            = *(uint32_t*)&a0;
        *(uint32_t*)&g_Zb[o + 2]        = *(uint32_t*)&a1;
        *(uint32_t*)&g_Zb[o + 1024]     = *(uint32_t*)&b0;
        *(uint32_t*)&g_Zb[o + 1026]     = *(uint32_t*)&b1;
    }
}

// weight converts: sel 0: W1h->Wst top; 1: W2h->(-Wst bottom, +W2hb);
//                  2: Wh1->Wh1b; 3: Wh2->Wh2b
__global__ void convw_kernel(const float* __restrict__ src, int sel, int n) {
    int i = blockIdx.x * blockDim.x + threadIdx.x;
    int stride = gridDim.x * blockDim.x;
    for (int idx = i * 4; idx < n; idx += stride * 4) {
        float4 v = *(const float4*)&src[idx];
        __nv_bfloat162 lo = __floats2bfloat162_rn(v.x, v.y);
        __nv_bfloat162 hi = __floats2bfloat162_rn(v.z, v.w);
        if (sel == 0) {
            *(uint32_t*)&g_Wst[idx]     = *(uint32_t*)&lo;
            *(uint32_t*)&g_Wst[idx + 2] = *(uint32_t*)&hi;
        } else if (sel == 1) {
            __nv_bfloat162 nlo = __floats2bfloat162_rn(-v.x, -v.y);
            __nv_bfloat162 nhi = __floats2bfloat162_rn(-v.z, -v.w);
            *(uint32_t*)&g_Wst[(size_t)1024 * 2048 + idx]     = *(uint32_t*)&nlo;
            *(uint32_t*)&g_Wst[(size_t)1024 * 2048 + idx + 2] = *(uint32_t*)&nhi;
            *(uint32_t*)&g_W2hb[idx]     = *(uint32_t*)&lo;
            *(uint32_t*)&g_W2hb[idx + 2] = *(uint32_t*)&hi;
        } else {
            __nv_bfloat16* dst = (sel == 2) ? g_Wh1b : g_Wh2b;
            *(uint32_t*)&dst[idx]     = *(uint32_t*)&lo;
            *(uint32_t*)&dst[idx + 2] = *(uint32_t*)&hi;
        }
    }
}

__global__ void init_kernel(const float* __restrict__ b1h,
                            const float* __restrict__ b2h,
                            const float* __restrict__ bh1,
                            const float* __restrict__ bh2) {
    int i = blockIdx.x * blockDim.x + threadIdx.x;
    if (i < NR) { g_row1[i] = 0.f; g_row2[i] = 0.f; g_row3[i] = 0.f; }
    if (i < 2048) g_db[i] = b1h[i] - b2h[i];
    if (i < 1024) { g_b12[i] = bh2[i]; g_b21[i] = bh1[i]; }
}

// b12[j] += sum_k b1h[k]*Wh2[k][j]  (partial k-ranges, atomic)
__global__ void bcomp_kernel(const float* __restrict__ bh,
                             const float* __restrict__ W, int sel) {
    float* out = sel ? g_b21 : g_b12;
    int j = blockIdx.x * 256 + threadIdx.x;
    int k0 = blockIdx.y * 128;
    float s = 0.f;
    #pragma unroll 4
    for (int k = k0; k < k0 + 128; k++) s += bh[k] * W[(size_t)k * 1024 + j];
    atomicAdd(&out[j], s);
}

// v[i] = W1h[i]·who (i<1024), v[1024+i] = W2h[i]·who  (warp per row, fp32)
__global__ void vcomp_kernel(const float* __restrict__ W1h,
                             const float* __restrict__ W2h,
                             const float* __restrict__ who) {
    int w = (blockIdx.x * blockDim.x + threadIdx.x) >> 5;
    int lane = threadIdx.x & 31;
    if (w >= 2048) return;
    const float* row = (w < 1024) ? &W1h[(size_t)w * 2048]
                                  : &W2h[(size_t)(w - 1024) * 2048];
    float s = 0.f;
    for (int k = lane; k < 2048; k += 32) s += row[k] * who[k];
    #pragma unroll
    for (int o = 16; o; o >>= 1) s += __shfl_xor_sync(0xffffffffu, s, o);
    if (lane == 0) g_v[w] = s;
}

__global__ void c0_kernel(const float* __restrict__ b1h,
                          const float* __restrict__ b2h,
                          const float* __restrict__ who,
                          const float* __restrict__ whob) {
    float s = 0.f;
    for (int k = threadIdx.x; k < 2048; k += 32)
        s += (b1h[k] + b2h[k]) * who[k];
    #pragma unroll
    for (int o = 16; o; o >>= 1) s += __shfl_xor_sync(0xffffffffu, s, o);
    if (threadIdx.x == 0) g_c0[0] = s + whob[0];
}

// ---------------- GEMM core (mma.sync bf16, 128x128x32, proven in R3) -------
// EPI 0 (gemmM): C = A*B -> bf16 M12/M21.         K=2048, ldb=1024
// EPI 1 (gemmX): row += sum (C + bias - Xref)^2.  K=1024, ldb=1024, aoff=z*1024
// EPI 2 (gemmL3): row += sum (C + db)^2.          K=2048, ldb=2048
template<int EPI>
__launch_bounds__(256, 2)
__global__ void gemm_core(const float* __restrict__ xr0,
                          const float* __restrict__ xr1) {
    constexpr int K   = (EPI == 1) ? 1024 : 2048;
    constexpr int LDB = (EPI == 2) ? 2048 : 1024;
    const int z = blockIdx.z;

    const __nv_bfloat16 *A, *B;
    __nv_bfloat16* C = nullptr;
    float* R = nullptr;
    const float* bias = nullptr;
    const float* Xref = nullptr;
    int aoff = 0;
    if (EPI == 0) {
        A = z ? g_W2hb : g_Wst;  B = z ? g_Wh1b : g_Wh2b;
        C = z ? g_M21 : g_M12;
    } else if (EPI == 2) {
        A = g_Zb;  B = g_Wst;  R = g_row3;  bias = g_db;
    } else {
        A = g_Zb;  B = z ? g_M21 : g_M12;
        R = z ? g_row2 : g_row1;  bias = z ? g_b21 : g_b12;
        Xref = z ? xr1 : xr0;  aoff = z * 1024;
    }
    constexpr int LDA = 2048;

    __shared__ __align__(16) __nv_bfloat16 smA[2][128][40];
    __shared__ __align__(16) __nv_bfloat16 smB[2][32][136];

    const int tid = threadIdx.x, lane = tid & 31, wid = tid >> 5;
    const int wm = wid >> 2, wn = wid & 3;
    const int brow = blockIdx.y * 128, bcol = blockIdx.x * 128;

    float c[4][4][4];
    #pragma unroll
    for (int i = 0; i < 4; i++)
        #pragma unroll
        for (int j = 0; j < 4; j++)
            #pragma unroll
            for (int k = 0; k < 4; k++) c[i][j][k] = 0.f;

    auto loadA = [&](int st, int k0) {
        #pragma unroll
        for (int i = 0; i < 2; i++) {
            int id = tid + i * 256;
            int r = id >> 2, kc = (id & 3) * 8;
            cp16(smem_u32(&smA[st][r][kc]),
                 &A[(size_t)(brow + r) * LDA + aoff + k0 + kc]);
        }
    };
    auto loadB = [&](int st, int k0) {
        #pragma unroll
        for (int i = 0; i < 2; i++) {
            int id = tid + i * 256;
            int r = id >> 4, nc = (id & 15) * 8;
            cp16(smem_u32(&smB[st][r][nc]),
                 &B[(size_t)(k0 + r) * LDB + bcol + nc]);
        }
    };

    loadA(0, 0); loadB(0, 0); CP_COMMIT;
    constexpr int nk = K / 32;
    for (int kt = 0; kt < nk; kt++) {
        const int cur = kt & 1, nxt = cur ^ 1;
        if (kt + 1 < nk) { loadA(nxt, (kt + 1) * 32); loadB(nxt, (kt + 1) * 32);
                           CP_COMMIT; CP_WAIT(1); }
        else             { CP_WAIT(0); }
        __syncthreads();

        #pragma unroll
        for (int ks = 0; ks < 32; ks += 16) {
            uint32_t a[4][4];
            #pragma unroll
            for (int mt = 0; mt < 4; mt++) {
                uint32_t ad = smem_u32(
                    &smA[cur][wm * 64 + mt * 16 + (lane & 15)][ks + (lane >> 4) * 8]);
                asm volatile(
                    "ldmatrix.sync.aligned.m8n8.x4.shared.b16 {%0,%1,%2,%3},[%4];"
                    : "=r"(a[mt][0]), "=r"(a[mt][1]), "=r"(a[mt][2]), "=r"(a[mt][3])
                    : "r"(ad));
            }
            uint32_t b[2][4];
            #pragma unroll
            for (int np = 0; np < 2; np++) {
                uint32_t ad = smem_u32(
                    &smB[cur][ks + (lane & 15)][wn * 32 + np * 16 + (lane >> 4) * 8]);
                asm volatile(
                    "ldmatrix.sync.aligned.m8n8.x4.trans.shared.b16 {%0,%1,%2,%3},[%4];"
                    : "=r"(b[np][0]), "=r"(b[np][1]), "=r"(b[np][2]), "=r"(b[np][3])
                    : "r"(ad));
            }
            #pragma unroll
            for (int mt = 0; mt < 4; mt++)
                #pragma unroll
                for (int nt = 0; nt < 4; nt++) {
                    uint32_t b0 = b[nt >> 1][(nt & 1) * 2];
                    uint32_t b1 = b[nt >> 1][(nt & 1) * 2 + 1];
                    asm volatile(
                        "mma.sync.aligned.m16n8k16.row.col.f32.bf16.bf16.f32 "
                        "{%0,%1,%2,%3},{%4,%5,%6,%7},{%8,%9},{%0,%1,%2,%3};"
                        : "+f"(c[mt][nt][0]), "+f"(c[mt][nt][1]),
                          "+f"(c[mt][nt][2]), "+f"(c[mt][nt][3])
                        : "r"(a[mt][0]), "r"(a[mt][1]), "r"(a[mt][2]), "r"(a[mt][3]),
                          "r"(b0), "r"(b1));
                }
        }
        __syncthreads();
    }

    if (EPI == 0) {
        #pragma unroll
        for (int mt = 0; mt < 4; mt++) {
            int r0 = brow + wm * 64 + mt * 16 + (lane >> 2);
            #pragma unroll
            for (int nt = 0; nt < 4; nt++) {
                int col = bcol + wn * 32 + nt * 8 + 2 * (lane & 3);
                __nv_bfloat162 v0 = __floats2bfloat162_rn(c[mt][nt][0], c[mt][nt][1]);
                __nv_bfloat162 v1 = __floats2bfloat162_rn(c[mt][nt][2], c[mt][nt][3]);
                *(__nv_bfloat162*)&C[(size_t)r0 * LDB + col] = v0;
                *(__nv_bfloat162*)&C[(size_t)(r0 + 8) * LDB + col] = v1;
            }
        }
    } else {
        #pragma unroll
        for (int mt = 0; mt < 4; mt++)
            #pragma unroll
            for (int half = 0; half < 2; half++) {
                int r = brow + wm * 64 + mt * 16 + (lane >> 2) + half * 8;
                float s = 0.f;
                #pragma unroll
                for (int nt = 0; nt < 4; nt++) {
                    int col = bcol + wn * 32 + nt * 8 + 2 * (lane & 3);
                    float d0 = c[mt][nt][half * 2 + 0] + bias[col];
                    float d1 = c[mt][nt][half * 2 + 1] + bias[col + 1];
                    if (EPI == 1) {
                        const float* xr = &Xref[(size_t)r * 1024 + col];
                        d0 -= xr[0]; d1 -= xr[1];
                    }
                    s += d0 * d0 + d1 * d1;
                }
                s += __shfl_xor_sync(0xffffffffu, s, 1);
                s += __shfl_xor_sync(0xffffffffu, s, 2);
                if ((lane & 3) == 0) atomicAdd(&R[r], s);
            }
    }
}

// ---------------- L4 per row (warp per row) ---------------------------------
__global__ void l4_kernel(const float* __restrict__ Y) {
    int w = (blockIdx.x * blockDim.x + threadIdx.x) >> 5;
    int lane = threadIdx.x & 31;
    const __nv_bfloat16* zr = &g_Zb[(size_t)w * 2048];
    float dot = 0.f;
    for (int k = lane * 4; k < 2048; k += 128) {
        uint2 u = *(const uint2*)&zr[k];
        float4 v = *(const float4*)&g_v[k];
        float2 a = __bfloat1622float2(*(__nv_bfloat162*)&u.x);
        float2 b = __bfloat1622float2(*(__nv_bfloat162*)&u.y);
        dot += a.x * v.x + a.y * v.y + b.x * v.z + b.y * v.w;
    }
    #pragma unroll
    for (int o = 16; o; o >>= 1) dot += __shfl_xor_sync(0xffffffffu, dot, o);
    if (lane == 0) {
        float L4 = 0.5f * (dot + g_c0[0]) - Y[w];
        g_L4sq[w] = L4 * L4;
    }
}

// ---------------- final scalar reduction (double) ---------------------------
__global__ void final_reduce_kernel(float* out) {
    __shared__ double sm[32];
    double s = 0.0;
    for (int r = threadIdx.x; r < NR; r += 1024) {
        double a = (double)g_row1[r], b = (double)g_row2[r], d = (double)g_row3[r];
        s += a * a + b * b + d * d + (double)g_L4sq[r];
    }
    #pragma unroll
    for (int o = 16; o; o >>= 1) s += __shfl_xor_sync(0xffffffffu, s, o);
    if ((threadIdx.x & 31) == 0) sm[threadIdx.x >> 5] = s;
    __syncthreads();
    if (threadIdx.x < 32) {
        double v = sm[threadIdx.x];
        #pragma unroll
        for (int o = 16; o; o >>= 1) v += __shfl_xor_sync(0xffffffffu, v, o);
        if (threadIdx.x == 0) out[0] = (float)v;
    }
}

// ---------------- launch -----------------------------------------------------
extern "C" void kernel_launch(void* const* d_in, const int* in_sizes, int n_in,
                              void* d_out, int out_size) {
    const float* X1   = (const float*)d_in[0];
    const float* X2   = (const float*)d_in[1];
    const float* Y    = (const float*)d_in[2];
    const float* w1hW = (const float*)d_in[3];
    const float* w1hb = (const float*)d_in[4];
    const float* w2hW = (const float*)d_in[5];
    const float* w2hb = (const float*)d_in[6];
    const float* wh1W = (const float*)d_in[7];
    const float* wh1b = (const float*)d_in[8];
    const float* wh2W = (const float*)d_in[9];
    const float* wh2b = (const float*)d_in[10];
    const float* whoW = (const float*)d_in[11];
    const float* whob = (const float*)d_in[12];

    convz_kernel<<<2048, 256>>>(X1, X2);
    convw_kernel<<<1024, 256>>>(w1hW, 0, DX * DH);
    convw_kernel<<<1024, 256>>>(w2hW, 1, DX * DH);
    convw_kernel<<<1024, 256>>>(wh1W, 2, DH * DX);
    convw_kernel<<<1024, 256>>>(wh2W, 3, DH * DX);
    init_kernel<<<64, 256>>>(w1hb, w2hb, wh1b, wh2b);
    bcomp_kernel<<<dim3(4, 16), 256>>>(w1hb, wh2W, 0);
    bcomp_kernel<<<dim3(4, 16), 256>>>(w2hb, wh1W, 1);
    vcomp_kernel<<<256, 256>>>(w1hW, w2hW, whoW);
    c0_kernel<<<1, 32>>>(w1hb, w2hb, whoW, whob);

    gemm_core<0><<<dim3(8, 8, 2),    256>>>(nullptr, nullptr);  // M12, M21
    gemm_core<2><<<dim3(16, 128, 1), 256>>>(nullptr, nullptr);  // L3 rows
    gemm_core<1><<<dim3(8, 128, 2),  256>>>(X2, X1);            // L1, L2 rows
    l4_kernel<<<NR / 8, 256>>>(Y);

    final_reduce_kernel<<<1, 1024>>>((float*)d_out);
}

// round 8
// speedup vs baseline: 1.2105x; 1.0077x over previous
#include <cuda_runtime.h>
#include <cuda_bf16.h>
#include <cstdint>
#include <cstddef>

#define NR 16384
#define DX 1024
#define DH 2048

// ---------------- device scratch (no dynamic allocation allowed) -----------
__device__ __align__(16) __nv_bfloat16 g_Zb[(size_t)NR * 2048];     // [X1|X2]
__device__ __align__(16) __nv_bfloat16 g_Wst[(size_t)2048 * 2048];  // [W1h;-W2h]
__device__ __align__(16) __nv_bfloat16 g_W2hb[(size_t)1024 * 2048];
__device__ __align__(16) __nv_bfloat16 g_Wh1b[(size_t)2048 * 1024];
__device__ __align__(16) __nv_bfloat16 g_Wh2b[(size_t)2048 * 1024];
__device__ __align__(16) __nv_bfloat16 g_M12[(size_t)1024 * 1024];
__device__ __align__(16) __nv_bfloat16 g_M21[(size_t)1024 * 1024];
__device__ float g_b12[1024];
__device__ float g_b21[1024];
__device__ float g_db[2048];
__device__ float g_v[2048];
__device__ float g_c0[1];
__device__ float g_row1[NR];
__device__ float g_row2[NR];
__device__ float g_row3[NR];
__device__ float g_L4sq[NR];

// ---------------- helpers --------------------------------------------------
__device__ __forceinline__ uint32_t smem_u32(const void* p) {
    uint32_t a;
    asm("{ .reg .u64 t; cvta.to.shared.u64 t, %1; cvt.u32.u64 %0, t; }"
        : "=r"(a) : "l"(p));
    return a;
}
__device__ __forceinline__ void cp16(uint32_t dst, const void* src) {
    uint64_t g;
    asm("cvta.to.global.u64 %0, %1;" : "=l"(g) : "l"(src));
    asm volatile("cp.async.cg.shared.global [%0], [%1], 16;"
                 :: "r"(dst), "l"(g) : "memory");
}
#define CP_COMMIT asm volatile("cp.async.commit_group;" ::: "memory")
#define CP_WAIT(n) asm volatile("cp.async.wait_group %0;" :: "n"(n) : "memory")

// ---------------- converts / init ------------------------------------------
// Z[r][0:1024] = bf16(X1[r]), Z[r][1024:2048] = bf16(X2[r]); streaming.
__global__ void convz_kernel(const float* __restrict__ X1,
                             const float* __restrict__ X2) {
    int i = blockIdx.x * blockDim.x + threadIdx.x;
    int stride = gridDim.x * blockDim.x;
    for (; i < NR * 256; i += stride) {
        int r = i >> 8, c = (i & 255) * 4;
        float4 a = __ldcs((const float4*)&X1[(size_t)r * 1024 + c]);
        float4 b = __ldcs((const float4*)&X2[(size_t)r * 1024 + c]);
        __nv_bfloat162 a0 = __floats2bfloat162_rn(a.x, a.y);
        __nv_bfloat162 a1 = __floats2bfloat162_rn(a.z, a.w);
        __nv_bfloat162 b0 = __floats2bfloat162_rn(b.x, b.y);
        __nv_bfloat162 b1 = __floats2bfloat162_rn(b.z, b.w);
        size_t o = (size_t)r * 2048 + c;
        __stcs((uint32_t*)&g_Zb[o],        *(uint32_t*)&a0);
        __stcs((uint32_t*)&g_Zb[o + 2],    *(uint32_t*)&a1);
        __stcs((uint32_t*)&g_Zb[o + 1024], *(uint32_t*)&b0);
        __stcs((uint32_t*)&g_Zb[o + 1026], *(uint32_t*)&b1);
    }
}

// one launch for all weight converts.
// sel 0: W1h->Wst top; 1: W2h->(-Wst bottom, +W2hb); 2: Wh1->Wh1b; 3: Wh2->Wh2b
__global__ void convw_kernel(const float* __restrict__ w1hW,
                             const float* __restrict__ w2hW,
                             const float* __restrict__ wh1W,
                             const float* __restrict__ wh2W) {
    const int NW = DX * DH / 4;                 // float4 groups per weight
    int i = blockIdx.x * blockDim.x + threadIdx.x;
    int stride = gridDim.x * blockDim.x;
    for (; i < 4 * NW; i += stride) {
        int sel = i / NW;
        int idx = (i - sel * NW) * 4;
        const float* src = (sel == 0) ? w1hW : (sel == 1) ? w2hW
                          : (sel == 2) ? wh1W : wh2W;
        float4 v = __ldcs((const float4*)&src[idx]);
        __nv_bfloat162 lo = __floats2bfloat162_rn(v.x, v.y);
        __nv_bfloat162 hi = __floats2bfloat162_rn(v.z, v.w);
        if (sel == 0) {
            *(uint32_t*)&g_Wst[idx]     = *(uint32_t*)&lo;
            *(uint32_t*)&g_Wst[idx + 2] = *(uint32_t*)&hi;
        } else if (sel == 1) {
            __nv_bfloat162 nlo = __floats2bfloat162_rn(-v.x, -v.y);
            __nv_bfloat162 nhi = __floats2bfloat162_rn(-v.z, -v.w);
            *(uint32_t*)&g_Wst[(size_t)1024 * 2048 + idx]     = *(uint32_t*)&nlo;
            *(uint32_t*)&g_Wst[(size_t)1024 * 2048 + idx + 2] = *(uint32_t*)&nhi;
            *(uint32_t*)&g_W2hb[idx]     = *(uint32_t*)&lo;
            *(uint32_t*)&g_W2hb[idx + 2] = *(uint32_t*)&hi;
        } else {
            __nv_bfloat16* dst = (sel == 2) ? g_Wh1b : g_Wh2b;
            *(uint32_t*)&dst[idx]     = *(uint32_t*)&lo;
            *(uint32_t*)&dst[idx + 2] = *(uint32_t*)&hi;
        }
    }
}

__global__ void init_kernel(const float* __restrict__ b1h,
                            const float* __restrict__ b2h,
                            const float* __restrict__ bh1,
                            const float* __restrict__ bh2) {
    int i = blockIdx.x * blockDim.x + threadIdx.x;
    if (i < NR) { g_row1[i] = 0.f; g_row2[i] = 0.f; g_row3[i] = 0.f; }
    if (i < 2048) g_db[i] = b1h[i] - b2h[i];
    if (i < 1024) { g_b12[i] = bh2[i]; g_b21[i] = bh1[i]; }
}

// b12[j] += sum_k b1h[k]*Wh2[k][j]  (partial k-ranges, atomic)
__global__ void bcomp_kernel(const float* __restrict__ bh,
                             const float* __restrict__ W, int sel) {
    float* out = sel ? g_b21 : g_b12;
    int j = blockIdx.x * 256 + threadIdx.x;
    int k0 = blockIdx.y * 128;
    float s = 0.f;
    #pragma unroll 4
    for (int k = k0; k < k0 + 128; k++) s += bh[k] * W[(size_t)k * 1024 + j];
    atomicAdd(&out[j], s);
}

// v[i] = W1h[i]·who (i<1024), v[1024+i] = W2h[i]·who
__global__ void vcomp_kernel(const float* __restrict__ W1h,
                             const float* __restrict__ W2h,
                             const float* __restrict__ who) {
    int w = (blockIdx.x * blockDim.x + threadIdx.x) >> 5;
    int lane = threadIdx.x & 31;
    if (w >= 2048) return;
    const float* row = (w < 1024) ? &W1h[(size_t)w * 2048]
                                  : &W2h[(size_t)(w - 1024) * 2048];
    float s = 0.f;
    for (int k = lane; k < 2048; k += 32) s += row[k] * who[k];
    #pragma unroll
    for (int o = 16; o; o >>= 1) s += __shfl_xor_sync(0xffffffffu, s, o);
    if (lane == 0) g_v[w] = s;
}

__global__ void c0_kernel(const float* __restrict__ b1h,
                          const float* __restrict__ b2h,
                          const float* __restrict__ who,
                          const float* __restrict__ whob) {
    float s = 0.f;
    for (int k = threadIdx.x; k < 2048; k += 32)
        s += (b1h[k] + b2h[k]) * who[k];
    #pragma unroll
    for (int o = 16; o; o >>= 1) s += __shfl_xor_sync(0xffffffffu, s, o);
    if (threadIdx.x == 0) g_c0[0] = s + whob[0];
}

// ---------------- GEMM core (mma.sync bf16, TMx128x32) ----------------------
// EPI 0 (TM=64):  C = A*B -> bf16 M12/M21.        K=2048, ldb=1024
// EPI 1 (TM=128): row += sum (C + bias - Zref)^2. K=1024, ldb=1024
// EPI 2 (TM=128): row += sum (C + db)^2.          K=2048, ldb=2048
template<int EPI, int TM>
__launch_bounds__(256, 2)
__global__ void gemm_core() {
    constexpr int K   = (EPI == 1) ? 1024 : 2048;
    constexpr int LDB = (EPI == 2) ? 2048 : 1024;
    constexpr int MT  = TM / 32;           // 16-row tiles per warp
    const int z = blockIdx.z;

    const __nv_bfloat16 *A, *B;
    __nv_bfloat16* C = nullptr;
    float* R = nullptr;
    const float* bias = nullptr;
    int aoff = 0, xoff = 0;
    if (EPI == 0) {
        A = z ? g_W2hb : g_Wst;  B = z ? g_Wh1b : g_Wh2b;
        C = z ? g_M21 : g_M12;
    } else if (EPI == 2) {
        A = g_Zb;  B = g_Wst;  R = g_row3;  bias = g_db;
    } else {
        A = g_Zb;  B = z ? g_M21 : g_M12;
        R = z ? g_row2 : g_row1;  bias = z ? g_b21 : g_b12;
        aoff = z * 1024;  xoff = z ? 0 : 1024;   // ref = other half of Z
    }
    constexpr int LDA = 2048;

    __shared__ __align__(16) __nv_bfloat16 smA[2][TM][40];
    __shared__ __align__(16) __nv_bfloat16 smB[2][32][136];

    const int tid = threadIdx.x, lane = tid & 31, wid = tid >> 5;
    const int wm = wid >> 2, wn = wid & 3;
    const int brow = blockIdx.y * TM, bcol = blockIdx.x * 128;

    float c[MT][4][4];
    #pragma unroll
    for (int i = 0; i < MT; i++)
        #pragma unroll
        for (int j = 0; j < 4; j++)
            #pragma unroll
            for (int k = 0; k < 4; k++) c[i][j][k] = 0.f;

    auto loadA = [&](int st, int k0) {
        #pragma unroll
        for (int i = 0; i < TM / 64; i++) {
            int id = tid + i * 256;
            int r = id >> 2, kc = (id & 3) * 8;
            cp16(smem_u32(&smA[st][r][kc]),
                 &A[(size_t)(brow + r) * LDA + aoff + k0 + kc]);
        }
    };
    auto loadB = [&](int st, int k0) {
        #pragma unroll
        for (int i = 0; i < 2; i++) {
            int id = tid + i * 256;
            int r = id >> 4, nc = (id & 15) * 8;
            cp16(smem_u32(&smB[st][r][nc]),
                 &B[(size_t)(k0 + r) * LDB + bcol + nc]);
        }
    };

    loadA(0, 0); loadB(0, 0); CP_COMMIT;
    constexpr int nk = K / 32;
    for (int kt = 0; kt < nk; kt++) {
        const int cur = kt & 1, nxt = cur ^ 1;
        if (kt + 1 < nk) { loadA(nxt, (kt + 1) * 32); loadB(nxt, (kt + 1) * 32);
                           CP_COMMIT; CP_WAIT(1); }
        else             { CP_WAIT(0); }
        __syncthreads();

        #pragma unroll
        for (int ks = 0; ks < 32; ks += 16) {
            uint32_t a[MT][4];
            #pragma unroll
            for (int mt = 0; mt < MT; mt++) {
                uint32_t ad = smem_u32(
                    &smA[cur][wm * (TM / 2) + mt * 16 + (lane & 15)]
                        [ks + (lane >> 4) * 8]);
                asm volatile(
                    "ldmatrix.sync.aligned.m8n8.x4.shared.b16 {%0,%1,%2,%3},[%4];"
                    : "=r"(a[mt][0]), "=r"(a[mt][1]), "=r"(a[mt][2]), "=r"(a[mt][3])
                    : "r"(ad));
            }
            uint32_t b[2][4];
            #pragma unroll
            for (int np = 0; np < 2; np++) {
                uint32_t ad = smem_u32(
                    &smB[cur][ks + (lane & 15)][wn * 32 + np * 16 + (lane >> 4) * 8]);
                asm volatile(
                    "ldmatrix.sync.aligned.m8n8.x4.trans.shared.b16 {%0,%1,%2,%3},[%4];"
                    : "=r"(b[np][0]), "=r"(b[np][1]), "=r"(b[np][2]), "=r"(b[np][3])
                    : "r"(ad));
            }
            #pragma unroll
            for (int mt = 0; mt < MT; mt++)
                #pragma unroll
                for (int nt = 0; nt < 4; nt++) {
                    uint32_t b0 = b[nt >> 1][(nt & 1) * 2];
                    uint32_t b1 = b[nt >> 1][(nt & 1) * 2 + 1];
                    asm volatile(
                        "mma.sync.aligned.m16n8k16.row.col.f32.bf16.bf16.f32 "
                        "{%0,%1,%2,%3},{%4,%5,%6,%7},{%8,%9},{%0,%1,%2,%3};"
                        : "+f"(c[mt][nt][0]), "+f"(c[mt][nt][1]),
                          "+f"(c[mt][nt][2]), "+f"(c[mt][nt][3])
                        : "r"(a[mt][0]), "r"(a[mt][1]), "r"(a[mt][2]), "r"(a[mt][3]),
                          "r"(b0), "r"(b1));
                }
        }
        __syncthreads();
    }

    if (EPI == 0) {
        #pragma unroll
        for (int mt = 0; mt < MT; mt++) {
            int r0 = brow + wm * (TM / 2) + mt * 16 + (lane >> 2);
            #pragma unroll
            for (int nt = 0; nt < 4; nt++) {
                int col = bcol + wn * 32 + nt * 8 + 2 * (lane & 3);
                __nv_bfloat162 v0 = __floats2bfloat162_rn(c[mt][nt][0], c[mt][nt][1]);
                __nv_bfloat162 v1 = __floats2bfloat162_rn(c[mt][nt][2], c[mt][nt][3]);
                *(__nv_bfloat162*)&C[(size_t)r0 * LDB + col] = v0;
                *(__nv_bfloat162*)&C[(size_t)(r0 + 8) * LDB + col] = v1;
            }
        }
    } else {
        #pragma unroll
        for (int mt = 0; mt < MT; mt++)
            #pragma unroll
            for (int half = 0; half < 2; half++) {
                int r = brow + wm * (TM / 2) + mt * 16 + (lane >> 2) + half * 8;
                float s = 0.f;
                #pragma unroll
                for (int nt = 0; nt < 4; nt++) {
                    int col = bcol + wn * 32 + nt * 8 + 2 * (lane & 3);
                    float d0 = c[mt][nt][half * 2 + 0] + bias[col];
                    float d1 = c[mt][nt][half * 2 + 1] + bias[col + 1];
                    if (EPI == 1) {
                        __nv_bfloat162 xz =
                            *(const __nv_bfloat162*)&g_Zb[(size_t)r * 2048 + xoff + col];
                        float2 xf = __bfloat1622float2(xz);
                        d0 -= xf.x; d1 -= xf.y;
                    }
                    s += d0 * d0 + d1 * d1;
                }
                s += __shfl_xor_sync(0xffffffffu, s, 1);
                s += __shfl_xor_sync(0xffffffffu, s, 2);
                if ((lane & 3) == 0) atomicAdd(&R[r], s);
            }
    }
}

// ---------------- L4 per row (warp per row) ---------------------------------
__global__ void l4_kernel(const float* __restrict__ Y) {
    int w = (blockIdx.x * blockDim.x + threadIdx.x) >> 5;
    int lane = threadIdx.x & 31;
    const __nv_bfloat16* zr = &g_Zb[(size_t)w * 2048];
    float dot = 0.f;
    for (int k = lane * 4; k < 2048; k += 128) {
        uint2 u = *(const uint2*)&zr[k];
        float4 v = *(const float4*)&g_v[k];
        float2 a = __bfloat1622float2(*(__nv_bfloat162*)&u.x);
        float2 b = __bfloat1622float2(*(__nv_bfloat162*)&u.y);
        dot += a.x * v.x + a.y * v.y + b.x * v.z + b.y * v.w;
    }
    #pragma unroll
    for (int o = 16; o; o >>= 1) dot += __shfl_xor_sync(0xffffffffu, dot, o);
    if (lane == 0) {
        float L4 = 0.5f * (dot + g_c0[0]) - Y[w];
        g_L4sq[w] = L4 * L4;
    }
}

// ---------------- final scalar reduction (double) ---------------------------
__global__ void final_reduce_kernel(float* out) {
    __shared__ double sm[32];
    double s = 0.0;
    for (int r = threadIdx.x; r < NR; r += 1024) {
        double a = (double)g_row1[r], b = (double)g_row2[r], d = (double)g_row3[r];
        s += a * a + b * b + d * d + (double)g_L4sq[r];
    }
    #pragma unroll
    for (int o = 16; o; o >>= 1) s += __shfl_xor_sync(0xffffffffu, s, o);
    if ((threadIdx.x & 31) == 0) sm[threadIdx.x >> 5] = s;
    __syncthreads();
    if (threadIdx.x < 32) {
        double v = sm[threadIdx.x];
        #pragma unroll
        for (int o = 16; o; o >>= 1) v += __shfl_xor_sync(0xffffffffu, v, o);
        if (threadIdx.x == 0) out[0] = (float)v;
    }
}

// ---------------- launch -----------------------------------------------------
extern "C" void kernel_launch(void* const* d_in, const int* in_sizes, int n_in,
                              void* d_out, int out_size) {
    const float* X1   = (const float*)d_in[0];
    const float* X2   = (const float*)d_in[1];
    const float* Y    = (const float*)d_in[2];
    const float* w1hW = (const float*)d_in[3];
    const float* w1hb = (const float*)d_in[4];
    const float* w2hW = (const float*)d_in[5];
    const float* w2hb = (const float*)d_in[6];
    const float* wh1W = (const float*)d_in[7];
    const float* wh1b = (const float*)d_in[8];
    const float* wh2W = (const float*)d_in[9];
    const float* wh2b = (const float*)d_in[10];
    const float* whoW = (const float*)d_in[11];
    const float* whob = (const float*)d_in[12];

    convz_kernel<<<4096, 256>>>(X1, X2);
    convw_kernel<<<4096, 256>>>(w1hW, w2hW, wh1W, wh2W);
    init_kernel<<<64, 256>>>(w1hb, w2hb, wh1b, wh2b);
    bcomp_kernel<<<dim3(4, 16), 256>>>(w1hb, wh2W, 0);
    bcomp_kernel<<<dim3(4, 16), 256>>>(w2hb, wh1W, 1);
    vcomp_kernel<<<256, 256>>>(w1hW, w2hW, whoW);
    c0_kernel<<<1, 32>>>(w1hb, w2hb, whoW, whob);

    gemm_core<0, 64> <<<dim3(8, 16, 2),  256>>>();  // M12, M21 (better util)
    gemm_core<2, 128><<<dim3(16, 128, 1), 256>>>(); // L3 rows
    gemm_core<1, 128><<<dim3(8, 128, 2),  256>>>(); // L1, L2 rows
    l4_kernel<<<NR / 8, 256>>>(Y);

    final_reduce_kernel<<<1, 1024>>>((float*)d_out);
}

// round 9
// speedup vs baseline: 1.2722x; 1.0510x over previous
#include <cuda_runtime.h>
#include <cuda_bf16.h>
#include <cstdint>
#include <cstddef>

#define NR 16384
#define DX 1024
#define DH 2048

// ---------------- device scratch (no dynamic allocation allowed) -----------
__device__ __align__(16) __nv_bfloat16 g_Zb[(size_t)NR * 2048];     // [X1|X2]
__device__ __align__(16) __nv_bfloat16 g_Wst[(size_t)2048 * 2048];  // [W1h;-W2h]
__device__ __align__(16) __nv_bfloat16 g_W2hb[(size_t)1024 * 2048];
__device__ __align__(16) __nv_bfloat16 g_Wh1b[(size_t)2048 * 1024];
__device__ __align__(16) __nv_bfloat16 g_Wh2b[(size_t)2048 * 1024];
__device__ __align__(16) __nv_bfloat16 g_M12[(size_t)1024 * 1024];
__device__ __align__(16) __nv_bfloat16 g_M21[(size_t)1024 * 1024];
__device__ float g_b12[1024];
__device__ float g_b21[1024];
__device__ float g_db[2048];
__device__ float g_v[2048];
__device__ float g_c0[1];
__device__ float g_row1[NR];
__device__ float g_row2[NR];
__device__ float g_row3[NR];
__device__ float g_L4sq[NR];

// ---------------- helpers --------------------------------------------------
__device__ __forceinline__ uint32_t smem_u32(const void* p) {
    uint32_t a;
    asm("{ .reg .u64 t; cvta.to.shared.u64 t, %1; cvt.u32.u64 %0, t; }"
        : "=r"(a) : "l"(p));
    return a;
}
__device__ __forceinline__ void cp16(uint32_t dst, const void* src) {
    uint64_t g;
    asm("cvta.to.global.u64 %0, %1;" : "=l"(g) : "l"(src));
    asm volatile("cp.async.cg.shared.global [%0], [%1], 16;"
                 :: "r"(dst), "l"(g) : "memory");
}
#define CP_COMMIT asm volatile("cp.async.commit_group;" ::: "memory")
#define CP_WAIT(n) asm volatile("cp.async.wait_group %0;" :: "n"(n) : "memory")

// ---------------- converts / init ------------------------------------------
// Z[r][0:1024] = bf16(X1[r]), Z[r][1024:2048] = bf16(X2[r]); streaming.
__global__ void convz_kernel(const float* __restrict__ X1,
                             const float* __restrict__ X2) {
    int i = blockIdx.x * blockDim.x + threadIdx.x;
    int stride = gridDim.x * blockDim.x;
    for (; i < NR * 256; i += stride) {
        int r = i >> 8, c = (i & 255) * 4;
        float4 a = __ldcs((const float4*)&X1[(size_t)r * 1024 + c]);
        float4 b = __ldcs((const float4*)&X2[(size_t)r * 1024 + c]);
        __nv_bfloat162 a0 = __floats2bfloat162_rn(a.x, a.y);
        __nv_bfloat162 a1 = __floats2bfloat162_rn(a.z, a.w);
        __nv_bfloat162 b0 = __floats2bfloat162_rn(b.x, b.y);
        __nv_bfloat162 b1 = __floats2bfloat162_rn(b.z, b.w);
        size_t o = (size_t)r * 2048 + c;
        __stcs((uint32_t*)&g_Zb[o],        *(uint32_t*)&a0);
        __stcs((uint32_t*)&g_Zb[o + 2],    *(uint32_t*)&a1);
        __stcs((uint32_t*)&g_Zb[o + 1024], *(uint32_t*)&b0);
        __stcs((uint32_t*)&g_Zb[o + 1026], *(uint32_t*)&b1);
    }
}

// one launch for all weight converts.
// sel 0: W1h->Wst top; 1: W2h->(-Wst bottom, +W2hb); 2: Wh1->Wh1b; 3: Wh2->Wh2b
__global__ void convw_kernel(const float* __restrict__ w1hW,
                             const float* __restrict__ w2hW,
                             const float* __restrict__ wh1W,
                             const float* __restrict__ wh2W) {
    const int NW = DX * DH / 4;
    int i = blockIdx.x * blockDim.x + threadIdx.x;
    int stride = gridDim.x * blockDim.x;
    for (; i < 4 * NW; i += stride) {
        int sel = i / NW;
        int idx = (i - sel * NW) * 4;
        const float* src = (sel == 0) ? w1hW : (sel == 1) ? w2hW
                          : (sel == 2) ? wh1W : wh2W;
        float4 v = __ldcs((const float4*)&src[idx]);
        __nv_bfloat162 lo = __floats2bfloat162_rn(v.x, v.y);
        __nv_bfloat162 hi = __floats2bfloat162_rn(v.z, v.w);
        if (sel == 0) {
            *(uint32_t*)&g_Wst[idx]     = *(uint32_t*)&lo;
            *(uint32_t*)&g_Wst[idx + 2] = *(uint32_t*)&hi;
        } else if (sel == 1) {
            __nv_bfloat162 nlo = __floats2bfloat162_rn(-v.x, -v.y);
            __nv_bfloat162 nhi = __floats2bfloat162_rn(-v.z, -v.w);
            *(uint32_t*)&g_Wst[(size_t)1024 * 2048 + idx]     = *(uint32_t*)&nlo;
            *(uint32_t*)&g_Wst[(size_t)1024 * 2048 + idx + 2] = *(uint32_t*)&nhi;
            *(uint32_t*)&g_W2hb[idx]     = *(uint32_t*)&lo;
            *(uint32_t*)&g_W2hb[idx + 2] = *(uint32_t*)&hi;
        } else {
            __nv_bfloat16* dst = (sel == 2) ? g_Wh1b : g_Wh2b;
            *(uint32_t*)&dst[idx]     = *(uint32_t*)&lo;
            *(uint32_t*)&dst[idx + 2] = *(uint32_t*)&hi;
        }
    }
}

__global__ void init_kernel(const float* __restrict__ b1h,
                            const float* __restrict__ b2h,
                            const float* __restrict__ bh1,
                            const float* __restrict__ bh2) {
    int i = blockIdx.x * blockDim.x + threadIdx.x;
    if (i < NR) { g_row1[i] = 0.f; g_row2[i] = 0.f; g_row3[i] = 0.f; }
    if (i < 2048) g_db[i] = b1h[i] - b2h[i];
    if (i < 1024) { g_b12[i] = bh2[i]; g_b21[i] = bh1[i]; }
}

// b12[j] += sum_k b1h[k]*Wh2[k][j]; b21[j] += sum_k b2h[k]*Wh1[k][j]
// grid (4, 128, 2): j-tile 256, k-chunk 16, z selects target. 1024 CTAs.
__global__ void bcomp_kernel(const float* __restrict__ b1h,
                             const float* __restrict__ b2h,
                             const float* __restrict__ wh2W,
                             const float* __restrict__ wh1W) {
    const int sel = blockIdx.z;
    const float* bh = sel ? b2h : b1h;
    const float* W  = sel ? wh1W : wh2W;
    float* out = sel ? g_b21 : g_b12;
    int j = blockIdx.x * 256 + threadIdx.x;
    int k0 = blockIdx.y * 16;
    float s = 0.f;
    #pragma unroll
    for (int k = 0; k < 16; k++)
        s += bh[k0 + k] * W[(size_t)(k0 + k) * 1024 + j];
    atomicAdd(&out[j], s);
}

// v[i] = W1h[i]·who (i<1024), v[1024+i] = W2h[i]·who; warp 2048 computes c0.
__global__ void vcomp_kernel(const float* __restrict__ W1h,
                             const float* __restrict__ W2h,
                             const float* __restrict__ who,
                             const float* __restrict__ b1h,
                             const float* __restrict__ b2h,
                             const float* __restrict__ whob) {
    int w = (blockIdx.x * blockDim.x + threadIdx.x) >> 5;
    int lane = threadIdx.x & 31;
    if (w > 2048) return;
    if (w == 2048) {
        float s = 0.f;
        for (int k = lane; k < 2048; k += 32)
            s += (b1h[k] + b2h[k]) * who[k];
        #pragma unroll
        for (int o = 16; o; o >>= 1) s += __shfl_xor_sync(0xffffffffu, s, o);
        if (lane == 0) g_c0[0] = s + whob[0];
        return;
    }
    const float* row = (w < 1024) ? &W1h[(size_t)w * 2048]
                                  : &W2h[(size_t)(w - 1024) * 2048];
    float s = 0.f;
    for (int k = lane; k < 2048; k += 32) s += row[k] * who[k];
    #pragma unroll
    for (int o = 16; o; o >>= 1) s += __shfl_xor_sync(0xffffffffu, s, o);
    if (lane == 0) g_v[w] = s;
}

// ---------------- GEMM core (mma.sync bf16, TMx128x32) ----------------------
// EPI 0 (TM=64):  C = A*B -> bf16 M12/M21.        K=2048, ldb=1024
// EPI 1 (TM=128): row += sum (C + bias - Zref)^2. K=1024, ldb=1024
// EPI 2 (TM=128): row += sum (C + db)^2.          K=2048, ldb=2048
template<int EPI, int TM>
__launch_bounds__(256, 2)
__global__ void gemm_core() {
    constexpr int K   = (EPI == 1) ? 1024 : 2048;
    constexpr int LDB = (EPI == 2) ? 2048 : 1024;
    constexpr int MT  = TM / 32;
    const int z = blockIdx.z;

    const __nv_bfloat16 *A, *B;
    __nv_bfloat16* C = nullptr;
    float* R = nullptr;
    const float* bias = nullptr;
    int aoff = 0, xoff = 0;
    if (EPI == 0) {
        A = z ? g_W2hb : g_Wst;  B = z ? g_Wh1b : g_Wh2b;
        C = z ? g_M21 : g_M12;
    } else if (EPI == 2) {
        A = g_Zb;  B = g_Wst;  R = g_row3;  bias = g_db;
    } else {
        A = g_Zb;  B = z ? g_M21 : g_M12;
        R = z ? g_row2 : g_row1;  bias = z ? g_b21 : g_b12;
        aoff = z * 1024;  xoff = z ? 0 : 1024;
    }
    constexpr int LDA = 2048;

    __shared__ __align__(16) __nv_bfloat16 smA[2][TM][40];
    __shared__ __align__(16) __nv_bfloat16 smB[2][32][136];

    const int tid = threadIdx.x, lane = tid & 31, wid = tid >> 5;
    const int wm = wid >> 2, wn = wid & 3;
    const int brow = blockIdx.y * TM, bcol = blockIdx.x * 128;

    float c[MT][4][4];
    #pragma unroll
    for (int i = 0; i < MT; i++)
        #pragma unroll
        for (int j = 0; j < 4; j++)
            #pragma unroll
            for (int k = 0; k < 4; k++) c[i][j][k] = 0.f;

    auto loadA = [&](int st, int k0) {
        #pragma unroll
        for (int i = 0; i < TM / 64; i++) {
            int id = tid + i * 256;
            int r = id >> 2, kc = (id & 3) * 8;
            cp16(smem_u32(&smA[st][r][kc]),
                 &A[(size_t)(brow + r) * LDA + aoff + k0 + kc]);
        }
    };
    auto loadB = [&](int st, int k0) {
        #pragma unroll
        for (int i = 0; i < 2; i++) {
            int id = tid + i * 256;
            int r = id >> 4, nc = (id & 15) * 8;
            cp16(smem_u32(&smB[st][r][nc]),
                 &B[(size_t)(k0 + r) * LDB + bcol + nc]);
        }
    };

    loadA(0, 0); loadB(0, 0); CP_COMMIT;
    constexpr int nk = K / 32;
    for (int kt = 0; kt < nk; kt++) {
        const int cur = kt & 1, nxt = cur ^ 1;
        if (kt + 1 < nk) { loadA(nxt, (kt + 1) * 32); loadB(nxt, (kt + 1) * 32);
                           CP_COMMIT; CP_WAIT(1); }
        else             { CP_WAIT(0); }
        __syncthreads();

        #pragma unroll
        for (int ks = 0; ks < 32; ks += 16) {
            uint32_t a[MT][4];
            #pragma unroll
            for (int mt = 0; mt < MT; mt++) {
                uint32_t ad = smem_u32(
                    &smA[cur][wm * (TM / 2) + mt * 16 + (lane & 15)]
                        [ks + (lane >> 4) * 8]);
                asm volatile(
                    "ldmatrix.sync.aligned.m8n8.x4.shared.b16 {%0,%1,%2,%3},[%4];"
                    : "=r"(a[mt][0]), "=r"(a[mt][1]), "=r"(a[mt][2]), "=r"(a[mt][3])
                    : "r"(ad));
            }
            uint32_t b[2][4];
            #pragma unroll
            for (int np = 0; np < 2; np++) {
                uint32_t ad = smem_u32(
                    &smB[cur][ks + (lane & 15)][wn * 32 + np * 16 + (lane >> 4) * 8]);
                asm volatile(
                    "ldmatrix.sync.aligned.m8n8.x4.trans.shared.b16 {%0,%1,%2,%3},[%4];"
                    : "=r"(b[np][0]), "=r"(b[np][1]), "=r"(b[np][2]), "=r"(b[np][3])
                    : "r"(ad));
            }
            #pragma unroll
            for (int mt = 0; mt < MT; mt++)
                #pragma unroll
                for (int nt = 0; nt < 4; nt++) {
                    uint32_t b0 = b[nt >> 1][(nt & 1) * 2];
                    uint32_t b1 = b[nt >> 1][(nt & 1) * 2 + 1];
                    asm volatile(
                        "mma.sync.aligned.m16n8k16.row.col.f32.bf16.bf16.f32 "
                        "{%0,%1,%2,%3},{%4,%5,%6,%7},{%8,%9},{%0,%1,%2,%3};"
                        : "+f"(c[mt][nt][0]), "+f"(c[mt][nt][1]),
                          "+f"(c[mt][nt][2]), "+f"(c[mt][nt][3])
                        : "r"(a[mt][0]), "r"(a[mt][1]), "r"(a[mt][2]), "r"(a[mt][3]),
                          "r"(b0), "r"(b1));
                }
        }
        __syncthreads();
    }

    if (EPI == 0) {
        #pragma unroll
        for (int mt = 0; mt < MT; mt++) {
            int r0 = brow + wm * (TM / 2) + mt * 16 + (lane >> 2);
            #pragma unroll
            for (int nt = 0; nt < 4; nt++) {
                int col = bcol + wn * 32 + nt * 8 + 2 * (lane & 3);
                __nv_bfloat162 v0 = __floats2bfloat162_rn(c[mt][nt][0], c[mt][nt][1]);
                __nv_bfloat162 v1 = __floats2bfloat162_rn(c[mt][nt][2], c[mt][nt][3]);
                *(__nv_bfloat162*)&C[(size_t)r0 * LDB + col] = v0;
                *(__nv_bfloat162*)&C[(size_t)(r0 + 8) * LDB + col] = v1;
            }
        }
    } else {
        #pragma unroll
        for (int mt = 0; mt < MT; mt++)
            #pragma unroll
            for (int half = 0; half < 2; half++) {
                int r = brow + wm * (TM / 2) + mt * 16 + (lane >> 2) + half * 8;
                float s = 0.f;
                #pragma unroll
                for (int nt = 0; nt < 4; nt++) {
                    int col = bcol + wn * 32 + nt * 8 + 2 * (lane & 3);
                    float d0 = c[mt][nt][half * 2 + 0] + bias[col];
                    float d1 = c[mt][nt][half * 2 + 1] + bias[col + 1];
                    if (EPI == 1) {
                        __nv_bfloat162 xz =
                            *(const __nv_bfloat162*)&g_Zb[(size_t)r * 2048 + xoff + col];
                        float2 xf = __bfloat1622float2(xz);
                        d0 -= xf.x; d1 -= xf.y;
                    }
                    s += d0 * d0 + d1 * d1;
                }
                s += __shfl_xor_sync(0xffffffffu, s, 1);
                s += __shfl_xor_sync(0xffffffffu, s, 2);
                if ((lane & 3) == 0) atomicAdd(&R[r], s);
            }
    }
}

// ---------------- L4 per row (warp per row) ---------------------------------
__global__ void l4_kernel(const float* __restrict__ Y) {
    int w = (blockIdx.x * blockDim.x + threadIdx.x) >> 5;
    int lane = threadIdx.x & 31;
    const __nv_bfloat16* zr = &g_Zb[(size_t)w * 2048];
    float dot = 0.f;
    for (int k = lane * 4; k < 2048; k += 128) {
        uint2 u = *(const uint2*)&zr[k];
        float4 v = *(const float4*)&g_v[k];
        float2 a = __bfloat1622float2(*(__nv_bfloat162*)&u.x);
        float2 b = __bfloat1622float2(*(__nv_bfloat162*)&u.y);
        dot += a.x * v.x + a.y * v.y + b.x * v.z + b.y * v.w;
    }
    #pragma unroll
    for (int o = 16; o; o >>= 1) dot += __shfl_xor_sync(0xffffffffu, dot, o);
    if (lane == 0) {
        float L4 = 0.5f * (dot + g_c0[0]) - Y[w];
        g_L4sq[w] = L4 * L4;
    }
}

// ---------------- final scalar reduction (double) ---------------------------
__global__ void final_reduce_kernel(float* out) {
    __shared__ double sm[32];
    double s = 0.0;
    for (int r = threadIdx.x; r < NR; r += 1024) {
        double a = (double)g_row1[r], b = (double)g_row2[r], d = (double)g_row3[r];
        s += a * a + b * b + d * d + (double)g_L4sq[r];
    }
    #pragma unroll
    for (int o = 16; o; o >>= 1) s += __shfl_xor_sync(0xffffffffu, s, o);
    if ((threadIdx.x & 31) == 0) sm[threadIdx.x >> 5] = s;
    __syncthreads();
    if (threadIdx.x < 32) {
        double v = sm[threadIdx.x];
        #pragma unroll
        for (int o = 16; o; o >>= 1) v += __shfl_xor_sync(0xffffffffu, v, o);
        if (threadIdx.x == 0) out[0] = (float)v;
    }
}

// ---------------- launch -----------------------------------------------------
extern "C" void kernel_launch(void* const* d_in, const int* in_sizes, int n_in,
                              void* d_out, int out_size) {
    const float* X1   = (const float*)d_in[0];
    const float* X2   = (const float*)d_in[1];
    const float* Y    = (const float*)d_in[2];
    const float* w1hW = (const float*)d_in[3];
    const float* w1hb = (const float*)d_in[4];
    const float* w2hW = (const float*)d_in[5];
    const float* w2hb = (const float*)d_in[6];
    const float* wh1W = (const float*)d_in[7];
    const float* wh1b = (const float*)d_in[8];
    const float* wh2W = (const float*)d_in[9];
    const float* wh2b = (const float*)d_in[10];
    const float* whoW = (const float*)d_in[11];
    const float* whob = (const float*)d_in[12];

    convz_kernel<<<4096, 256>>>(X1, X2);
    convw_kernel<<<4096, 256>>>(w1hW, w2hW, wh1W, wh2W);
    init_kernel<<<64, 256>>>(w1hb, w2hb, wh1b, wh2b);
    bcomp_kernel<<<dim3(4, 128, 2), 256>>>(w1hb, w2hb, wh2W, wh1W);
    vcomp_kernel<<<257, 256>>>(w1hW, w2hW, whoW, w1hb, w2hb, whob);

    gemm_core<0, 64> <<<dim3(8, 16, 2),   256>>>();  // M12, M21
    gemm_core<2, 128><<<dim3(16, 128, 1), 256>>>();  // L3 rows
    gemm_core<1, 128><<<dim3(8, 128, 2),  256>>>();  // L1, L2 rows
    l4_kernel<<<NR / 8, 256>>>(Y);

    final_reduce_kernel<<<1, 1024>>>((float*)d_out);
}

// round 10
// speedup vs baseline: 1.3040x; 1.0250x over previous
#include <cuda_runtime.h>
#include <cuda_bf16.h>
#include <cstdint>
#include <cstddef>

#define NR 16384
#define DX 1024
#define DH 2048

// ---------------- device scratch (no dynamic allocation allowed) -----------
__device__ __align__(16) __nv_bfloat16 g_Zb[(size_t)NR * 2048];     // [X1|X2]
__device__ __align__(16) __nv_bfloat16 g_Wst[(size_t)2048 * 2048];  // [W1h;-W2h]
__device__ __align__(16) __nv_bfloat16 g_W2hb[(size_t)1024 * 2048];
__device__ __align__(16) __nv_bfloat16 g_Wh1b[(size_t)2048 * 1024];
__device__ __align__(16) __nv_bfloat16 g_Wh2b[(size_t)2048 * 1024];
__device__ __align__(16) __nv_bfloat16 g_M12[(size_t)1024 * 1024];
__device__ __align__(16) __nv_bfloat16 g_M21[(size_t)1024 * 1024];
__device__ float g_b12[1024];
__device__ float g_b21[1024];
__device__ float g_db[2048];
__device__ float g_v[2048];
__device__ float g_c0[1];
__device__ float g_row1[NR];
__device__ float g_row2[NR];
__device__ float g_row3[NR];
__device__ float g_L4sq[NR];

// ---------------- helpers --------------------------------------------------
__device__ __forceinline__ uint32_t smem_u32(const void* p) {
    uint32_t a;
    asm("{ .reg .u64 t; cvta.to.shared.u64 t, %1; cvt.u32.u64 %0, t; }"
        : "=r"(a) : "l"(p));
    return a;
}
__device__ __forceinline__ void cp16(uint32_t dst, const void* src) {
    uint64_t g;
    asm("cvta.to.global.u64 %0, %1;" : "=l"(g) : "l"(src));
    asm volatile("cp.async.cg.shared.global [%0], [%1], 16;"
                 :: "r"(dst), "l"(g) : "memory");
}
#define CP_COMMIT asm volatile("cp.async.commit_group;" ::: "memory")
#define CP_WAIT(n) asm volatile("cp.async.wait_group %0;" :: "n"(n) : "memory")

// ---------------- converts / init ------------------------------------------
// Z[r][0:1024] = bf16(X1[r]), Z[r][1024:2048] = bf16(X2[r]); streaming.
__global__ void convz_kernel(const float* __restrict__ X1,
                             const float* __restrict__ X2) {
    int i = blockIdx.x * blockDim.x + threadIdx.x;
    int stride = gridDim.x * blockDim.x;
    for (; i < NR * 256; i += stride) {
        int r = i >> 8, c = (i & 255) * 4;
        float4 a = __ldcs((const float4*)&X1[(size_t)r * 1024 + c]);
        float4 b = __ldcs((const float4*)&X2[(size_t)r * 1024 + c]);
        __nv_bfloat162 a0 = __floats2bfloat162_rn(a.x, a.y);
        __nv_bfloat162 a1 = __floats2bfloat162_rn(a.z, a.w);
        __nv_bfloat162 b0 = __floats2bfloat162_rn(b.x, b.y);
        __nv_bfloat162 b1 = __floats2bfloat162_rn(b.z, b.w);
        size_t o = (size_t)r * 2048 + c;
        __stcs((uint32_t*)&g_Zb[o],        *(uint32_t*)&a0);
        __stcs((uint32_t*)&g_Zb[o + 2],    *(uint32_t*)&a1);
        __stcs((uint32_t*)&g_Zb[o + 1024], *(uint32_t*)&b0);
        __stcs((uint32_t*)&g_Zb[o + 1026], *(uint32_t*)&b1);
    }
}

// one launch for all weight converts.
// sel 0: W1h->Wst top; 1: W2h->(-Wst bottom, +W2hb); 2: Wh1->Wh1b; 3: Wh2->Wh2b
__global__ void convw_kernel(const float* __restrict__ w1hW,
                             const float* __restrict__ w2hW,
                             const float* __restrict__ wh1W,
                             const float* __restrict__ wh2W) {
    const int NW = DX * DH / 4;
    int i = blockIdx.x * blockDim.x + threadIdx.x;
    int stride = gridDim.x * blockDim.x;
    for (; i < 4 * NW; i += stride) {
        int sel = i / NW;
        int idx = (i - sel * NW) * 4;
        const float* src = (sel == 0) ? w1hW : (sel == 1) ? w2hW
                          : (sel == 2) ? wh1W : wh2W;
        float4 v = __ldcs((const float4*)&src[idx]);
        __nv_bfloat162 lo = __floats2bfloat162_rn(v.x, v.y);
        __nv_bfloat162 hi = __floats2bfloat162_rn(v.z, v.w);
        if (sel == 0) {
            *(uint32_t*)&g_Wst[idx]     = *(uint32_t*)&lo;
            *(uint32_t*)&g_Wst[idx + 2] = *(uint32_t*)&hi;
        } else if (sel == 1) {
            __nv_bfloat162 nlo = __floats2bfloat162_rn(-v.x, -v.y);
            __nv_bfloat162 nhi = __floats2bfloat162_rn(-v.z, -v.w);
            *(uint32_t*)&g_Wst[(size_t)1024 * 2048 + idx]     = *(uint32_t*)&nlo;
            *(uint32_t*)&g_Wst[(size_t)1024 * 2048 + idx + 2] = *(uint32_t*)&nhi;
            *(uint32_t*)&g_W2hb[idx]     = *(uint32_t*)&lo;
            *(uint32_t*)&g_W2hb[idx + 2] = *(uint32_t*)&hi;
        } else {
            __nv_bfloat16* dst = (sel == 2) ? g_Wh1b : g_Wh2b;
            *(uint32_t*)&dst[idx]     = *(uint32_t*)&lo;
            *(uint32_t*)&dst[idx + 2] = *(uint32_t*)&hi;
        }
    }
}

__global__ void init_kernel(const float* __restrict__ b1h,
                            const float* __restrict__ b2h,
                            const float* __restrict__ bh1,
                            const float* __restrict__ bh2) {
    int i = blockIdx.x * blockDim.x + threadIdx.x;
    if (i < NR) { g_row1[i] = 0.f; g_row2[i] = 0.f; g_row3[i] = 0.f; }
    if (i < 2048) g_db[i] = b1h[i] - b2h[i];
    if (i < 1024) { g_b12[i] = bh2[i]; g_b21[i] = bh1[i]; }
}

// b12[j] += sum_k b1h[k]*Wh2[k][j]; b21[j] += sum_k b2h[k]*Wh1[k][j]
__global__ void bcomp_kernel(const float* __restrict__ b1h,
                             const float* __restrict__ b2h,
                             const float* __restrict__ wh2W,
                             const float* __restrict__ wh1W) {
    const int sel = blockIdx.z;
    const float* bh = sel ? b2h : b1h;
    const float* W  = sel ? wh1W : wh2W;
    float* out = sel ? g_b21 : g_b12;
    int j = blockIdx.x * 256 + threadIdx.x;
    int k0 = blockIdx.y * 16;
    float s = 0.f;
    #pragma unroll
    for (int k = 0; k < 16; k++)
        s += bh[k0 + k] * W[(size_t)(k0 + k) * 1024 + j];
    atomicAdd(&out[j], s);
}

// v[i] = W1h[i]·who (i<1024), v[1024+i] = W2h[i]·who; warp 2048 computes c0.
__global__ void vcomp_kernel(const float* __restrict__ W1h,
                             const float* __restrict__ W2h,
                             const float* __restrict__ who,
                             const float* __restrict__ b1h,
                             const float* __restrict__ b2h,
                             const float* __restrict__ whob) {
    int w = (blockIdx.x * blockDim.x + threadIdx.x) >> 5;
    int lane = threadIdx.x & 31;
    if (w > 2048) return;
    if (w == 2048) {
        float s = 0.f;
        for (int k = lane; k < 2048; k += 32)
            s += (b1h[k] + b2h[k]) * who[k];
        #pragma unroll
        for (int o = 16; o; o >>= 1) s += __shfl_xor_sync(0xffffffffu, s, o);
        if (lane == 0) g_c0[0] = s + whob[0];
        return;
    }
    const float* row = (w < 1024) ? &W1h[(size_t)w * 2048]
                                  : &W2h[(size_t)(w - 1024) * 2048];
    float s = 0.f;
    for (int k = lane; k < 2048; k += 32) s += row[k] * who[k];
    #pragma unroll
    for (int o = 16; o; o >>= 1) s += __shfl_xor_sync(0xffffffffu, s, o);
    if (lane == 0) g_v[w] = s;
}

// ---------------- GEMM core (mma.sync bf16, TMx128x32) ----------------------
template<int EPI, int TM>
__launch_bounds__(256, 2)
__global__ void gemm_core() {
    constexpr int K   = (EPI == 1) ? 1024 : 2048;
    constexpr int LDB = (EPI == 2) ? 2048 : 1024;
    constexpr int MT  = TM / 32;
    const int z = blockIdx.z;

    const __nv_bfloat16 *A, *B;
    __nv_bfloat16* C = nullptr;
    float* R = nullptr;
    const float* bias = nullptr;
    int aoff = 0, xoff = 0;
    if (EPI == 0) {
        A = z ? g_W2hb : g_Wst;  B = z ? g_Wh1b : g_Wh2b;
        C = z ? g_M21 : g_M12;
    } else if (EPI == 2) {
        A = g_Zb;  B = g_Wst;  R = g_row3;  bias = g_db;
    } else {
        A = g_Zb;  B = z ? g_M21 : g_M12;
        R = z ? g_row2 : g_row1;  bias = z ? g_b21 : g_b12;
        aoff = z * 1024;  xoff = z ? 0 : 1024;
    }
    constexpr int LDA = 2048;

    __shared__ __align__(16) __nv_bfloat16 smA[2][TM][40];
    __shared__ __align__(16) __nv_bfloat16 smB[2][32][136];

    const int tid = threadIdx.x, lane = tid & 31, wid = tid >> 5;
    const int wm = wid >> 2, wn = wid & 3;
    const int brow = blockIdx.y * TM, bcol = blockIdx.x * 128;

    float c[MT][4][4];
    #pragma unroll
    for (int i = 0; i < MT; i++)
        #pragma unroll
        for (int j = 0; j < 4; j++)
            #pragma unroll
            for (int k = 0; k < 4; k++) c[i][j][k] = 0.f;

    auto loadA = [&](int st, int k0) {
        #pragma unroll
        for (int i = 0; i < TM / 64; i++) {
            int id = tid + i * 256;
            int r = id >> 2, kc = (id & 3) * 8;
            cp16(smem_u32(&smA[st][r][kc]),
                 &A[(size_t)(brow + r) * LDA + aoff + k0 + kc]);
        }
    };
    auto loadB = [&](int st, int k0) {
        #pragma unroll
        for (int i = 0; i < 2; i++) {
            int id = tid + i * 256;
            int r = id >> 4, nc = (id & 15) * 8;
            cp16(smem_u32(&smB[st][r][nc]),
                 &B[(size_t)(k0 + r) * LDB + bcol + nc]);
        }
    };

    loadA(0, 0); loadB(0, 0); CP_COMMIT;
    constexpr int nk = K / 32;
    for (int kt = 0; kt < nk; kt++) {
        const int cur = kt & 1, nxt = cur ^ 1;
        if (kt + 1 < nk) { loadA(nxt, (kt + 1) * 32); loadB(nxt, (kt + 1) * 32);
                           CP_COMMIT; CP_WAIT(1); }
        else             { CP_WAIT(0); }
        __syncthreads();

        #pragma unroll
        for (int ks = 0; ks < 32; ks += 16) {
            uint32_t a[MT][4];
            #pragma unroll
            for (int mt = 0; mt < MT; mt++) {
                uint32_t ad = smem_u32(
                    &smA[cur][wm * (TM / 2) + mt * 16 + (lane & 15)]
                        [ks + (lane >> 4) * 8]);
                asm volatile(
                    "ldmatrix.sync.aligned.m8n8.x4.shared.b16 {%0,%1,%2,%3},[%4];"
                    : "=r"(a[mt][0]), "=r"(a[mt][1]), "=r"(a[mt][2]), "=r"(a[mt][3])
                    : "r"(ad));
            }
            uint32_t b[2][4];
            #pragma unroll
            for (int np = 0; np < 2; np++) {
                uint32_t ad = smem_u32(
                    &smB[cur][ks + (lane & 15)][wn * 32 + np * 16 + (lane >> 4) * 8]);
                asm volatile(
                    "ldmatrix.sync.aligned.m8n8.x4.trans.shared.b16 {%0,%1,%2,%3},[%4];"
                    : "=r"(b[np][0]), "=r"(b[np][1]), "=r"(b[np][2]), "=r"(b[np][3])
                    : "r"(ad));
            }
            #pragma unroll
            for (int mt = 0; mt < MT; mt++)
                #pragma unroll
                for (int nt = 0; nt < 4; nt++) {
                    uint32_t b0 = b[nt >> 1][(nt & 1) * 2];
                    uint32_t b1 = b[nt >> 1][(nt & 1) * 2 + 1];
                    asm volatile(
                        "mma.sync.aligned.m16n8k16.row.col.f32.bf16.bf16.f32 "
                        "{%0,%1,%2,%3},{%4,%5,%6,%7},{%8,%9},{%0,%1,%2,%3};"
                        : "+f"(c[mt][nt][0]), "+f"(c[mt][nt][1]),
                          "+f"(c[mt][nt][2]), "+f"(c[mt][nt][3])
                        : "r"(a[mt][0]), "r"(a[mt][1]), "r"(a[mt][2]), "r"(a[mt][3]),
                          "r"(b0), "r"(b1));
                }
        }
        __syncthreads();
    }

    if (EPI == 0) {
        #pragma unroll
        for (int mt = 0; mt < MT; mt++) {
            int r0 = brow + wm * (TM / 2) + mt * 16 + (lane >> 2);
            #pragma unroll
            for (int nt = 0; nt < 4; nt++) {
                int col = bcol + wn * 32 + nt * 8 + 2 * (lane & 3);
                __nv_bfloat162 v0 = __floats2bfloat162_rn(c[mt][nt][0], c[mt][nt][1]);
                __nv_bfloat162 v1 = __floats2bfloat162_rn(c[mt][nt][2], c[mt][nt][3]);
                *(__nv_bfloat162*)&C[(size_t)r0 * LDB + col] = v0;
                *(__nv_bfloat162*)&C[(size_t)(r0 + 8) * LDB + col] = v1;
            }
        }
    } else {
        #pragma unroll
        for (int mt = 0; mt < MT; mt++)
            #pragma unroll
            for (int half = 0; half < 2; half++) {
                int r = brow + wm * (TM / 2) + mt * 16 + (lane >> 2) + half * 8;
                float s = 0.f;
                #pragma unroll
                for (int nt = 0; nt < 4; nt++) {
                    int col = bcol + wn * 32 + nt * 8 + 2 * (lane & 3);
                    float d0 = c[mt][nt][half * 2 + 0] + bias[col];
                    float d1 = c[mt][nt][half * 2 + 1] + bias[col + 1];
                    if (EPI == 1) {
                        __nv_bfloat162 xz =
                            *(const __nv_bfloat162*)&g_Zb[(size_t)r * 2048 + xoff + col];
                        float2 xf = __bfloat1622float2(xz);
                        d0 -= xf.x; d1 -= xf.y;
                    }
                    s += d0 * d0 + d1 * d1;
                }
                s += __shfl_xor_sync(0xffffffffu, s, 1);
                s += __shfl_xor_sync(0xffffffffu, s, 2);
                if ((lane & 3) == 0) atomicAdd(&R[r], s);
            }
    }
}

// ---------------- L4 per row (warp per row) ---------------------------------
__global__ void l4_kernel(const float* __restrict__ Y) {
    int w = (blockIdx.x * blockDim.x + threadIdx.x) >> 5;
    int lane = threadIdx.x & 31;
    const __nv_bfloat16* zr = &g_Zb[(size_t)w * 2048];
    float dot = 0.f;
    for (int k = lane * 4; k < 2048; k += 128) {
        uint2 u = *(const uint2*)&zr[k];
        float4 v = *(const float4*)&g_v[k];
        float2 a = __bfloat1622float2(*(__nv_bfloat162*)&u.x);
        float2 b = __bfloat1622float2(*(__nv_bfloat162*)&u.y);
        dot += a.x * v.x + a.y * v.y + b.x * v.z + b.y * v.w;
    }
    #pragma unroll
    for (int o = 16; o; o >>= 1) dot += __shfl_xor_sync(0xffffffffu, dot, o);
    if (lane == 0) {
        float L4 = 0.5f * (dot + g_c0[0]) - Y[w];
        g_L4sq[w] = L4 * L4;
    }
}

// ---------------- final scalar reduction (double) ---------------------------
__global__ void final_reduce_kernel(float* out) {
    __shared__ double sm[32];
    double s = 0.0;
    for (int r = threadIdx.x; r < NR; r += 1024) {
        double a = (double)g_row1[r], b = (double)g_row2[r], d = (double)g_row3[r];
        s += a * a + b * b + d * d + (double)g_L4sq[r];
    }
    #pragma unroll
    for (int o = 16; o; o >>= 1) s += __shfl_xor_sync(0xffffffffu, s, o);
    if ((threadIdx.x & 31) == 0) sm[threadIdx.x >> 5] = s;
    __syncthreads();
    if (threadIdx.x < 32) {
        double v = sm[threadIdx.x];
        #pragma unroll
        for (int o = 16; o; o >>= 1) v += __shfl_xor_sync(0xffffffffu, v, o);
        if (threadIdx.x == 0) out[0] = (float)v;
    }
}

// ---------------- launch -----------------------------------------------------
extern "C" void kernel_launch(void* const* d_in, const int* in_sizes, int n_in,
                              void* d_out, int out_size) {
    const float* X1   = (const float*)d_in[0];
    const float* X2   = (const float*)d_in[1];
    const float* Y    = (const float*)d_in[2];
    const float* w1hW = (const float*)d_in[3];
    const float* w1hb = (const float*)d_in[4];
    const float* w2hW = (const float*)d_in[5];
    const float* w2hb = (const float*)d_in[6];
    const float* wh1W = (const float*)d_in[7];
    const float* wh1b = (const float*)d_in[8];
    const float* wh2W = (const float*)d_in[9];
    const float* wh2b = (const float*)d_in[10];
    const float* whoW = (const float*)d_in[11];
    const float* whob = (const float*)d_in[12];

    // Streams/events created once (host objects, not device memory).
    static cudaStream_t sA = nullptr, sB = nullptr, sC = nullptr;
    static cudaEvent_t evStart = nullptr, evZ = nullptr, evB = nullptr,
                       evL4 = nullptr;
    if (sA == nullptr) {
        cudaStreamCreateWithFlags(&sA, cudaStreamNonBlocking);
        cudaStreamCreateWithFlags(&sB, cudaStreamNonBlocking);
        cudaStreamCreateWithFlags(&sC, cudaStreamNonBlocking);
        cudaEventCreateWithFlags(&evStart, cudaEventDisableTiming);
        cudaEventCreateWithFlags(&evZ, cudaEventDisableTiming);
        cudaEventCreateWithFlags(&evB, cudaEventDisableTiming);
        cudaEventCreateWithFlags(&evL4, cudaEventDisableTiming);
    }

    // fork side branches off the main (captured) stream
    cudaEventRecord(evStart, 0);
    cudaStreamWaitEvent(sA, evStart, 0);
    cudaStreamWaitEvent(sB, evStart, 0);
    cudaStreamWaitEvent(sC, evStart, 0);

    // branch A: X -> Z conversion (DRAM-bound, overlaps convw + M-GEMM)
    convz_kernel<<<4096, 256, 0, sA>>>(X1, X2);
    cudaEventRecord(evZ, sA);

    // branch B: row zeroing + bias composition
    init_kernel<<<64, 256, 0, sB>>>(w1hb, w2hb, wh1b, wh2b);
    bcomp_kernel<<<dim3(4, 128, 2), 256, 0, sB>>>(w1hb, w2hb, wh2W, wh1W);
    cudaEventRecord(evB, sB);

    // branch C: v vector, then L4 (needs Z) — overlaps the big GEMMs
    vcomp_kernel<<<257, 256, 0, sC>>>(w1hW, w2hW, whoW, w1hb, w2hb, whob);
    cudaStreamWaitEvent(sC, evZ, 0);
    l4_kernel<<<NR / 8, 256, 0, sC>>>(Y);
    cudaEventRecord(evL4, sC);

    // main stream: weight convert -> M-GEMMs (need only weights)
    convw_kernel<<<4096, 256>>>(w1hW, w2hW, wh1W, wh2W);
    gemm_core<0, 64><<<dim3(8, 16, 2), 256>>>();       // M12, M21

    // join Z and bias branches, then the big GEMMs
    cudaStreamWaitEvent(0, evZ, 0);
    cudaStreamWaitEvent(0, evB, 0);
    gemm_core<2, 128><<<dim3(16, 128, 1), 256>>>();    // L3 rows
    gemm_core<1, 128><<<dim3(8, 128, 2), 256>>>();     // L1, L2 rows

    // join L4 branch, final reduction
    cudaStreamWaitEvent(0, evL4, 0);
    final_reduce_kernel<<<1, 1024>>>((float*)d_out);
}

// round 11
// speedup vs baseline: 1.3440x; 1.0307x over previous
#include <cuda_runtime.h>
#include <cuda_bf16.h>
#include <cstdint>
#include <cstddef>

#define NR 16384
#define DX 1024
#define DH 2048

// ---------------- device scratch (no dynamic allocation allowed) -----------
__device__ __align__(16) __nv_bfloat16 g_Zb[(size_t)NR * 2048];     // [X1|X2]
__device__ __align__(16) __nv_bfloat16 g_Wst[(size_t)2048 * 2048];  // [W1h;-W2h]
__device__ __align__(16) __nv_bfloat16 g_W2hb[(size_t)1024 * 2048];
__device__ __align__(16) __nv_bfloat16 g_Wh1b[(size_t)2048 * 1024];
__device__ __align__(16) __nv_bfloat16 g_Wh2b[(size_t)2048 * 1024];
__device__ __align__(16) __nv_bfloat16 g_M12[(size_t)1024 * 1024];
__device__ __align__(16) __nv_bfloat16 g_M21[(size_t)1024 * 1024];
__device__ float g_b12[1024];
__device__ float g_b21[1024];
__device__ float g_db[2048];
__device__ float g_v[2048];
__device__ float g_c0[1];
__device__ float g_row1[NR];
__device__ float g_row2[NR];
__device__ float g_row3[NR];
__device__ float g_L4sq[NR];

// ---------------- helpers --------------------------------------------------
__device__ __forceinline__ uint32_t smem_u32(const void* p) {
    uint32_t a;
    asm("{ .reg .u64 t; cvta.to.shared.u64 t, %1; cvt.u32.u64 %0, t; }"
        : "=r"(a) : "l"(p));
    return a;
}
__device__ __forceinline__ void cp16(uint32_t dst, const void* src) {
    uint64_t g;
    asm("cvta.to.global.u64 %0, %1;" : "=l"(g) : "l"(src));
    asm volatile("cp.async.cg.shared.global [%0], [%1], 16;"
                 :: "r"(dst), "l"(g) : "memory");
}
#define CP_COMMIT asm volatile("cp.async.commit_group;" ::: "memory")
#define CP_WAIT(n) asm volatile("cp.async.wait_group %0;" :: "n"(n) : "memory")

// ---------------- converts / init ------------------------------------------
__global__ void convz_kernel(const float* __restrict__ X1,
                             const float* __restrict__ X2) {
    int i = blockIdx.x * blockDim.x + threadIdx.x;
    int stride = gridDim.x * blockDim.x;
    for (; i < NR * 256; i += stride) {
        int r = i >> 8, c = (i & 255) * 4;
        float4 a = __ldcs((const float4*)&X1[(size_t)r * 1024 + c]);
        float4 b = __ldcs((const float4*)&X2[(size_t)r * 1024 + c]);
        __nv_bfloat162 a0 = __floats2bfloat162_rn(a.x, a.y);
        __nv_bfloat162 a1 = __floats2bfloat162_rn(a.z, a.w);
        __nv_bfloat162 b0 = __floats2bfloat162_rn(b.x, b.y);
        __nv_bfloat162 b1 = __floats2bfloat162_rn(b.z, b.w);
        size_t o = (size_t)r * 2048 + c;
        __stcs((uint32_t*)&g_Zb[o],        *(uint32_t*)&a0);
        __stcs((uint32_t*)&g_Zb[o + 2],    *(uint32_t*)&a1);
        __stcs((uint32_t*)&g_Zb[o + 1024], *(uint32_t*)&b0);
        __stcs((uint32_t*)&g_Zb[o + 1026], *(uint32_t*)&b1);
    }
}

__global__ void convw_kernel(const float* __restrict__ w1hW,
                             const float* __restrict__ w2hW,
                             const float* __restrict__ wh1W,
                             const float* __restrict__ wh2W) {
    const int NW = DX * DH / 4;
    int i = blockIdx.x * blockDim.x + threadIdx.x;
    int stride = gridDim.x * blockDim.x;
    for (; i < 4 * NW; i += stride) {
        int sel = i / NW;
        int idx = (i - sel * NW) * 4;
        const float* src = (sel == 0) ? w1hW : (sel == 1) ? w2hW
                          : (sel == 2) ? wh1W : wh2W;
        float4 v = __ldcs((const float4*)&src[idx]);
        __nv_bfloat162 lo = __floats2bfloat162_rn(v.x, v.y);
        __nv_bfloat162 hi = __floats2bfloat162_rn(v.z, v.w);
        if (sel == 0) {
            *(uint32_t*)&g_Wst[idx]     = *(uint32_t*)&lo;
            *(uint32_t*)&g_Wst[idx + 2] = *(uint32_t*)&hi;
        } else if (sel == 1) {
            __nv_bfloat162 nlo = __floats2bfloat162_rn(-v.x, -v.y);
            __nv_bfloat162 nhi = __floats2bfloat162_rn(-v.z, -v.w);
            *(uint32_t*)&g_Wst[(size_t)1024 * 2048 + idx]     = *(uint32_t*)&nlo;
            *(uint32_t*)&g_Wst[(size_t)1024 * 2048 + idx + 2] = *(uint32_t*)&nhi;
            *(uint32_t*)&g_W2hb[idx]     = *(uint32_t*)&lo;
            *(uint32_t*)&g_W2hb[idx + 2] = *(uint32_t*)&hi;
        } else {
            __nv_bfloat16* dst = (sel == 2) ? g_Wh1b : g_Wh2b;
            *(uint32_t*)&dst[idx]     = *(uint32_t*)&lo;
            *(uint32_t*)&dst[idx + 2] = *(uint32_t*)&hi;
        }
    }
}

__global__ void init_kernel(const float* __restrict__ b1h,
                            const float* __restrict__ b2h,
                            const float* __restrict__ bh1,
                            const float* __restrict__ bh2) {
    int i = blockIdx.x * blockDim.x + threadIdx.x;
    if (i < NR) { g_row1[i] = 0.f; g_row2[i] = 0.f; g_row3[i] = 0.f; }
    if (i < 2048) g_db[i] = b1h[i] - b2h[i];
    if (i < 1024) { g_b12[i] = bh2[i]; g_b21[i] = bh1[i]; }
}

__global__ void bcomp_kernel(const float* __restrict__ b1h,
                             const float* __restrict__ b2h,
                             const float* __restrict__ wh2W,
                             const float* __restrict__ wh1W) {
    const int sel = blockIdx.z;
    const float* bh = sel ? b2h : b1h;
    const float* W  = sel ? wh1W : wh2W;
    float* out = sel ? g_b21 : g_b12;
    int j = blockIdx.x * 256 + threadIdx.x;
    int k0 = blockIdx.y * 16;
    float s = 0.f;
    #pragma unroll
    for (int k = 0; k < 16; k++)
        s += bh[k0 + k] * W[(size_t)(k0 + k) * 1024 + j];
    atomicAdd(&out[j], s);
}

__global__ void vcomp_kernel(const float* __restrict__ W1h,
                             const float* __restrict__ W2h,
                             const float* __restrict__ who,
                             const float* __restrict__ b1h,
                             const float* __restrict__ b2h,
                             const float* __restrict__ whob) {
    int w = (blockIdx.x * blockDim.x + threadIdx.x) >> 5;
    int lane = threadIdx.x & 31;
    if (w > 2048) return;
    if (w == 2048) {
        float s = 0.f;
        for (int k = lane; k < 2048; k += 32)
            s += (b1h[k] + b2h[k]) * who[k];
        #pragma unroll
        for (int o = 16; o; o >>= 1) s += __shfl_xor_sync(0xffffffffu, s, o);
        if (lane == 0) g_c0[0] = s + whob[0];
        return;
    }
    const float* row = (w < 1024) ? &W1h[(size_t)w * 2048]
                                  : &W2h[(size_t)(w - 1024) * 2048];
    float s = 0.f;
    for (int k = lane; k < 2048; k += 32) s += row[k] * who[k];
    #pragma unroll
    for (int o = 16; o; o >>= 1) s += __shfl_xor_sync(0xffffffffu, s, o);
    if (lane == 0) g_v[w] = s;
}

// ---------------- M-GEMM (mma.sync bf16, 64x128x32) -------------------------
__launch_bounds__(256, 2)
__global__ void gemm_m() {
    const int z = blockIdx.z;
    const __nv_bfloat16* A = z ? g_W2hb : g_Wst;
    const __nv_bfloat16* B = z ? g_Wh1b : g_Wh2b;
    __nv_bfloat16* C = z ? g_M21 : g_M12;

    __shared__ __align__(16) __nv_bfloat16 smA[2][64][40];
    __shared__ __align__(16) __nv_bfloat16 smB[2][32][136];

    const int tid = threadIdx.x, lane = tid & 31, wid = tid >> 5;
    const int wm = wid >> 2, wn = wid & 3;
    const int brow = blockIdx.y * 64, bcol = blockIdx.x * 128;

    float c[2][4][4];
    #pragma unroll
    for (int i = 0; i < 2; i++)
        #pragma unroll
        for (int j = 0; j < 4; j++)
            #pragma unroll
            for (int k = 0; k < 4; k++) c[i][j][k] = 0.f;

    auto loadA = [&](int st, int k0) {
        int r = tid >> 2, kc = (tid & 3) * 8;
        cp16(smem_u32(&smA[st][r][kc]),
             &A[(size_t)(brow + r) * 2048 + k0 + kc]);
    };
    auto loadB = [&](int st, int k0) {
        #pragma unroll
        for (int i = 0; i < 2; i++) {
            int id = tid + i * 256;
            int r = id >> 4, nc = (id & 15) * 8;
            cp16(smem_u32(&smB[st][r][nc]),
                 &B[(size_t)(k0 + r) * 1024 + bcol + nc]);
        }
    };

    loadA(0, 0); loadB(0, 0); CP_COMMIT;
    for (int kt = 0; kt < 64; kt++) {
        const int cur = kt & 1, nxt = cur ^ 1;
        if (kt + 1 < 64) { loadA(nxt, (kt + 1) * 32); loadB(nxt, (kt + 1) * 32);
                           CP_COMMIT; CP_WAIT(1); }
        else             { CP_WAIT(0); }
        __syncthreads();

        #pragma unroll
        for (int ks = 0; ks < 32; ks += 16) {
            uint32_t a[2][4];
            #pragma unroll
            for (int mt = 0; mt < 2; mt++) {
                uint32_t ad = smem_u32(
                    &smA[cur][wm * 32 + mt * 16 + (lane & 15)][ks + (lane >> 4) * 8]);
                asm volatile(
                    "ldmatrix.sync.aligned.m8n8.x4.shared.b16 {%0,%1,%2,%3},[%4];"
                    : "=r"(a[mt][0]), "=r"(a[mt][1]), "=r"(a[mt][2]), "=r"(a[mt][3])
                    : "r"(ad));
            }
            uint32_t b[2][4];
            #pragma unroll
            for (int np = 0; np < 2; np++) {
                uint32_t ad = smem_u32(
                    &smB[cur][ks + (lane & 15)][wn * 32 + np * 16 + (lane >> 4) * 8]);
                asm volatile(
                    "ldmatrix.sync.aligned.m8n8.x4.trans.shared.b16 {%0,%1,%2,%3},[%4];"
                    : "=r"(b[np][0]), "=r"(b[np][1]), "=r"(b[np][2]), "=r"(b[np][3])
                    : "r"(ad));
            }
            #pragma unroll
            for (int mt = 0; mt < 2; mt++)
                #pragma unroll
                for (int nt = 0; nt < 4; nt++) {
                    uint32_t b0 = b[nt >> 1][(nt & 1) * 2];
                    uint32_t b1 = b[nt >> 1][(nt & 1) * 2 + 1];
                    asm volatile(
                        "mma.sync.aligned.m16n8k16.row.col.f32.bf16.bf16.f32 "
                        "{%0,%1,%2,%3},{%4,%5,%6,%7},{%8,%9},{%0,%1,%2,%3};"
                        : "+f"(c[mt][nt][0]), "+f"(c[mt][nt][1]),
                          "+f"(c[mt][nt][2]), "+f"(c[mt][nt][3])
                        : "r"(a[mt][0]), "r"(a[mt][1]), "r"(a[mt][2]), "r"(a[mt][3]),
                          "r"(b0), "r"(b1));
                }
        }
        __syncthreads();
    }

    #pragma unroll
    for (int mt = 0; mt < 2; mt++) {
        int r0 = brow + wm * 32 + mt * 16 + (lane >> 2);
        #pragma unroll
        for (int nt = 0; nt < 4; nt++) {
            int col = bcol + wn * 32 + nt * 8 + 2 * (lane & 3);
            __nv_bfloat162 v0 = __floats2bfloat162_rn(c[mt][nt][0], c[mt][nt][1]);
            __nv_bfloat162 v1 = __floats2bfloat162_rn(c[mt][nt][2], c[mt][nt][3]);
            *(__nv_bfloat162*)&C[(size_t)r0 * 1024 + col] = v0;
            *(__nv_bfloat162*)&C[(size_t)(r0 + 8) * 1024 + col] = v1;
        }
    }
}

// ---------------- merged big GEMM: L3 + both X-GEMMs, one launch ------------
// grid (16, 128, 2). z=0: L3 tile (K=2048, B=Wst).   z=1: X-GEMMs
// (blockIdx.x>>3 selects zz; K=1024, B=M12/M21, subtract Z half).
__launch_bounds__(256, 2)
__global__ void gemm_big() {
    const int z = blockIdx.z;
    int bx = blockIdx.x;

    const __nv_bfloat16* B;
    float* R;
    const float* bias;
    int K, LDB, aoff, xoff, isx;
    if (z == 0) {
        B = g_Wst; R = g_row3; bias = g_db;
        K = 2048; LDB = 2048; aoff = 0; xoff = 0; isx = 0;
    } else {
        int zz = bx >> 3; bx &= 7;
        B = zz ? g_M21 : g_M12; R = zz ? g_row2 : g_row1;
        bias = zz ? g_b21 : g_b12;
        K = 1024; LDB = 1024; aoff = zz * 1024; xoff = zz ? 0 : 1024; isx = 1;
    }
    const __nv_bfloat16* A = g_Zb;

    __shared__ __align__(16) __nv_bfloat16 smA[2][128][40];
    __shared__ __align__(16) __nv_bfloat16 smB[2][32][136];

    const int tid = threadIdx.x, lane = tid & 31, wid = tid >> 5;
    const int wm = wid >> 2, wn = wid & 3;
    const int brow = blockIdx.y * 128, bcol = bx * 128;

    float c[4][4][4];
    #pragma unroll
    for (int i = 0; i < 4; i++)
        #pragma unroll
        for (int j = 0; j < 4; j++)
            #pragma unroll
            for (int k = 0; k < 4; k++) c[i][j][k] = 0.f;

    auto loadA = [&](int st, int k0) {
        #pragma unroll
        for (int i = 0; i < 2; i++) {
            int id = tid + i * 256;
            int r = id >> 2, kc = (id & 3) * 8;
            cp16(smem_u32(&smA[st][r][kc]),
                 &A[(size_t)(brow + r) * 2048 + aoff + k0 + kc]);
        }
    };
    auto loadB = [&](int st, int k0) {
        #pragma unroll
        for (int i = 0; i < 2; i++) {
            int id = tid + i * 256;
            int r = id >> 4, nc = (id & 15) * 8;
            cp16(smem_u32(&smB[st][r][nc]),
                 &B[(size_t)(k0 + r) * LDB + bcol + nc]);
        }
    };

    loadA(0, 0); loadB(0, 0); CP_COMMIT;
    const int nk = K / 32;
    for (int kt = 0; kt < nk; kt++) {
        const int cur = kt & 1, nxt = cur ^ 1;
        if (kt + 1 < nk) { loadA(nxt, (kt + 1) * 32); loadB(nxt, (kt + 1) * 32);
                           CP_COMMIT; CP_WAIT(1); }
        else             { CP_WAIT(0); }
        __syncthreads();

        #pragma unroll
        for (int ks = 0; ks < 32; ks += 16) {
            uint32_t a[4][4];
            #pragma unroll
            for (int mt = 0; mt < 4; mt++) {
                uint32_t ad = smem_u32(
                    &smA[cur][wm * 64 + mt * 16 + (lane & 15)][ks + (lane >> 4) * 8]);
                asm volatile(
                    "ldmatrix.sync.aligned.m8n8.x4.shared.b16 {%0,%1,%2,%3},[%4];"
                    : "=r"(a[mt][0]), "=r"(a[mt][1]), "=r"(a[mt][2]), "=r"(a[mt][3])
                    : "r"(ad));
            }
            uint32_t b[2][4];
            #pragma unroll
            for (int np = 0; np < 2; np++) {
                uint32_t ad = smem_u32(
                    &smB[cur][ks + (lane & 15)][wn * 32 + np * 16 + (lane >> 4) * 8]);
                asm volatile(
                    "ldmatrix.sync.aligned.m8n8.x4.trans.shared.b16 {%0,%1,%2,%3},[%4];"
                    : "=r"(b[np][0]), "=r"(b[np][1]), "=r"(b[np][2]), "=r"(b[np][3])
                    : "r"(ad));
            }
            #pragma unroll
            for (int mt = 0; mt < 4; mt++)
                #pragma unroll
                for (int nt = 0; nt < 4; nt++) {
                    uint32_t b0 = b[nt >> 1][(nt & 1) * 2];
                    uint32_t b1 = b[nt >> 1][(nt & 1) * 2 + 1];
                    asm volatile(
                        "mma.sync.aligned.m16n8k16.row.col.f32.bf16.bf16.f32 "
                        "{%0,%1,%2,%3},{%4,%5,%6,%7},{%8,%9},{%0,%1,%2,%3};"
                        : "+f"(c[mt][nt][0]), "+f"(c[mt][nt][1]),
                          "+f"(c[mt][nt][2]), "+f"(c[mt][nt][3])
                        : "r"(a[mt][0]), "r"(a[mt][1]), "r"(a[mt][2]), "r"(a[mt][3]),
                          "r"(b0), "r"(b1));
                }
        }
        __syncthreads();
    }

    #pragma unroll
    for (int mt = 0; mt < 4; mt++)
        #pragma unroll
        for (int half = 0; half < 2; half++) {
            int r = brow + wm * 64 + mt * 16 + (lane >> 2) + half * 8;
            float s = 0.f;
            #pragma unroll
            for (int nt = 0; nt < 4; nt++) {
                int col = bcol + wn * 32 + nt * 8 + 2 * (lane & 3);
                float d0 = c[mt][nt][half * 2 + 0] + bias[col];
                float d1 = c[mt][nt][half * 2 + 1] + bias[col + 1];
                if (isx) {
                    __nv_bfloat162 xz =
                        *(const __nv_bfloat162*)&g_Zb[(size_t)r * 2048 + xoff + col];
                    float2 xf = __bfloat1622float2(xz);
                    d0 -= xf.x; d1 -= xf.y;
                }
                s += d0 * d0 + d1 * d1;
            }
            s += __shfl_xor_sync(0xffffffffu, s, 1);
            s += __shfl_xor_sync(0xffffffffu, s, 2);
            if ((lane & 3) == 0) atomicAdd(&R[r], s);
        }
}

// ---------------- L4 per row (warp per row) ---------------------------------
__global__ void l4_kernel(const float* __restrict__ Y) {
    int w = (blockIdx.x * blockDim.x + threadIdx.x) >> 5;
    int lane = threadIdx.x & 31;
    const __nv_bfloat16* zr = &g_Zb[(size_t)w * 2048];
    float dot = 0.f;
    for (int k = lane * 4; k < 2048; k += 128) {
        uint2 u = *(const uint2*)&zr[k];
        float4 v = *(const float4*)&g_v[k];
        float2 a = __bfloat1622float2(*(__nv_bfloat162*)&u.x);
        float2 b = __bfloat1622float2(*(__nv_bfloat162*)&u.y);
        dot += a.x * v.x + a.y * v.y + b.x * v.z + b.y * v.w;
    }
    #pragma unroll
    for (int o = 16; o; o >>= 1) dot += __shfl_xor_sync(0xffffffffu, dot, o);
    if (lane == 0) {
        float L4 = 0.5f * (dot + g_c0[0]) - Y[w];
        g_L4sq[w] = L4 * L4;
    }
}

// ---------------- final scalar reduction (double) ---------------------------
__global__ void final_reduce_kernel(float* out) {
    __shared__ double sm[32];
    double s = 0.0;
    for (int r = threadIdx.x; r < NR; r += 1024) {
        double a = (double)g_row1[r], b = (double)g_row2[r], d = (double)g_row3[r];
        s += a * a + b * b + d * d + (double)g_L4sq[r];
    }
    #pragma unroll
    for (int o = 16; o; o >>= 1) s += __shfl_xor_sync(0xffffffffu, s, o);
    if ((threadIdx.x & 31) == 0) sm[threadIdx.x >> 5] = s;
    __syncthreads();
    if (threadIdx.x < 32) {
        double v = sm[threadIdx.x];
        #pragma unroll
        for (int o = 16; o; o >>= 1) v += __shfl_xor_sync(0xffffffffu, v, o);
        if (threadIdx.x == 0) out[0] = (float)v;
    }
}

// ---------------- launch -----------------------------------------------------
extern "C" void kernel_launch(void* const* d_in, const int* in_sizes, int n_in,
                              void* d_out, int out_size) {
    const float* X1   = (const float*)d_in[0];
    const float* X2   = (const float*)d_in[1];
    const float* Y    = (const float*)d_in[2];
    const float* w1hW = (const float*)d_in[3];
    const float* w1hb = (const float*)d_in[4];
    const float* w2hW = (const float*)d_in[5];
    const float* w2hb = (const float*)d_in[6];
    const float* wh1W = (const float*)d_in[7];
    const float* wh1b = (const float*)d_in[8];
    const float* wh2W = (const float*)d_in[9];
    const float* wh2b = (const float*)d_in[10];
    const float* whoW = (const float*)d_in[11];
    const float* whob = (const float*)d_in[12];

    static cudaStream_t sA = nullptr, sB = nullptr, sC = nullptr;
    static cudaEvent_t evStart = nullptr, evZ = nullptr, evB = nullptr,
                       evL4 = nullptr;
    if (sA == nullptr) {
        cudaStreamCreateWithFlags(&sA, cudaStreamNonBlocking);
        cudaStreamCreateWithFlags(&sB, cudaStreamNonBlocking);
        cudaStreamCreateWithFlags(&sC, cudaStreamNonBlocking);
        cudaEventCreateWithFlags(&evStart, cudaEventDisableTiming);
        cudaEventCreateWithFlags(&evZ, cudaEventDisableTiming);
        cudaEventCreateWithFlags(&evB, cudaEventDisableTiming);
        cudaEventCreateWithFlags(&evL4, cudaEventDisableTiming);
    }

    cudaEventRecord(evStart, 0);
    cudaStreamWaitEvent(sA, evStart, 0);
    cudaStreamWaitEvent(sB, evStart, 0);
    cudaStreamWaitEvent(sC, evStart, 0);

    // branch A: X -> Z conversion (overlaps convw + M-GEMM)
    convz_kernel<<<4096, 256, 0, sA>>>(X1, X2);
    cudaEventRecord(evZ, sA);

    // branch B: row zeroing + bias composition
    init_kernel<<<64, 256, 0, sB>>>(w1hb, w2hb, wh1b, wh2b);
    bcomp_kernel<<<dim3(4, 128, 2), 256, 0, sB>>>(w1hb, w2hb, wh2W, wh1W);
    cudaEventRecord(evB, sB);

    // branch C: v vector, then L4 (needs Z) — overlaps the big GEMM
    vcomp_kernel<<<257, 256, 0, sC>>>(w1hW, w2hW, whoW, w1hb, w2hb, whob);
    cudaStreamWaitEvent(sC, evZ, 0);
    l4_kernel<<<NR / 8, 256, 0, sC>>>(Y);
    cudaEventRecord(evL4, sC);

    // main: weight convert -> M-GEMMs (need only weights)
    convw_kernel<<<4096, 256>>>(w1hW, w2hW, wh1W, wh2W);
    gemm_m<<<dim3(8, 16, 2), 256>>>();                 // M12, M21

    // join Z and bias branches, then the single merged GEMM
    cudaStreamWaitEvent(0, evZ, 0);
    cudaStreamWaitEvent(0, evB, 0);
    gemm_big<<<dim3(16, 128, 2), 256>>>();             // L3 + L1 + L2

    cudaStreamWaitEvent(0, evL4, 0);
    final_reduce_kernel<<<1, 1024>>>((float*)d_out);
}